// round 2
// baseline (speedup 1.0000x reference)
#include <cuda_runtime.h>
#include <math.h>

#define B_   4
#define N_   2
#define NB   8          // B_*N_ flattened images
#define NC   256        // codes
#define CD   256        // channels
#define H_   96
#define W_   192
#define HW   (H_*W_)    // 18432

// Scratch (static __device__ per harness rules; .bss, not stored in binary)
__device__ float g_Wt[(size_t)NB * HW * NC];   // sigmoid weights, layout [b][p][n]
__device__ float g_Ws[(size_t)NB * HW * NC];   // softmaxed weights, layout [b][p][n]
__device__ float g_norm[NC];
__device__ int   g_masked[NC];
__device__ float g_theta[NB][6];

// ---------------------------------------------------------------------------
// Setup: per-code norm^2, cosine mask vs codebook_pub, theta copy.
// grid = NC blocks (one per code), 256 threads.
// ---------------------------------------------------------------------------
__global__ __launch_bounds__(256) void setup_kernel(const float* __restrict__ cb,
                                                    const float* __restrict__ pub,
                                                    const float* __restrict__ aff) {
    __shared__ float red[256];
    const int n = blockIdx.x, t = threadIdx.x;

    float v = cb[n * CD + t];
    red[t] = v * v;
    __syncthreads();
    for (int s = 128; s > 0; s >>= 1) { if (t < s) red[t] += red[t + s]; __syncthreads(); }
    const float cbn2 = red[0];
    __syncthreads();

    // thread t handles pub row t
    const float* cr = cb + n * CD;
    const float* pr = pub + t * CD;
    float dot = 0.f, pn2 = 0.f;
#pragma unroll 8
    for (int c = 0; c < CD; c++) {
        float pv = pr[c];
        dot = fmaf(cr[c], pv, dot);
        pn2 = fmaf(pv, pv, pn2);
    }
    red[t] = dot * rsqrtf(cbn2 * pn2);
    __syncthreads();
    for (int s = 128; s > 0; s >>= 1) { if (t < s) red[t] = fmaxf(red[t], red[t + s]); __syncthreads(); }

    if (t == 0) {
        g_masked[n] = (red[0] <= 0.5f) ? 1 : 0;
        g_norm[n]   = cbn2;
    }
    // theta[b'] = affine[bg][i][0][:][:], flattened b' = bg*N_+i  (stride b'=12)
    if (n == 0 && t < NB * 6) g_theta[t / 6][t % 6] = aff[(t / 6) * 12 + (t % 6)];
}

// ---------------------------------------------------------------------------
// GEMM1: Wt[b][p][n] = sigmoid( (sum_c feat[b][c][p] * cb[n][c]) / norm2[n] )
// 128x128 block tile, 8x8 micro-tile, K chunk 16.
// ---------------------------------------------------------------------------
__global__ __launch_bounds__(256) void gemm1_kernel(const float* __restrict__ feat,
                                                    const float* __restrict__ cb) {
    __shared__ float As[16][128];   // [c][p]
    __shared__ float Bs[16][128];   // [c][n]
    const int b  = blockIdx.z;
    const int p0 = blockIdx.x * 128;
    const int n0 = blockIdx.y * 128;
    const int tid  = threadIdx.x;
    const int lane = tid & 31, warp = tid >> 5;
    const int a_off = (warp >> 1) * 32 + (lane >> 3) * 8;   // p within tile
    const int b_off = (warp & 1) * 64 + (lane & 7) * 8;     // n within tile

    float acc[8][8] = {};

    const float* fbase = feat + (size_t)b * CD * HW + p0;
    const int lr = tid >> 5;         // 0..7 (c row for A load)
    const int lc = (tid & 31) * 4;   // 0..124 (p col)
    const int bn = tid >> 2;         // 0..63 (n for B load)
    const int bc = (tid & 3) * 4;    // 0..12 (c)

    for (int k0 = 0; k0 < CD; k0 += 16) {
#pragma unroll
        for (int pass = 0; pass < 2; pass++) {
            int r = lr + pass * 8;
            float4 f = *(const float4*)(fbase + (size_t)(k0 + r) * HW + lc);
            *(float4*)&As[r][lc] = f;
        }
#pragma unroll
        for (int pass = 0; pass < 2; pass++) {
            int n = bn + pass * 64;
            float4 f = *(const float4*)(cb + (size_t)(n0 + n) * CD + k0 + bc);
            Bs[bc + 0][n] = f.x; Bs[bc + 1][n] = f.y;
            Bs[bc + 2][n] = f.z; Bs[bc + 3][n] = f.w;
        }
        __syncthreads();
#pragma unroll
        for (int kc = 0; kc < 16; kc++) {
            float4 a0 = *(const float4*)&As[kc][a_off];
            float4 a1 = *(const float4*)&As[kc][a_off + 4];
            float4 b0 = *(const float4*)&Bs[kc][b_off];
            float4 b1 = *(const float4*)&Bs[kc][b_off + 4];
            float ar[8] = {a0.x, a0.y, a0.z, a0.w, a1.x, a1.y, a1.z, a1.w};
            float br[8] = {b0.x, b0.y, b0.z, b0.w, b1.x, b1.y, b1.z, b1.w};
#pragma unroll
            for (int i = 0; i < 8; i++)
#pragma unroll
                for (int j = 0; j < 8; j++)
                    acc[i][j] = fmaf(ar[i], br[j], acc[i][j]);
        }
        __syncthreads();
    }

    float inv_n[8];
#pragma unroll
    for (int j = 0; j < 8; j++) inv_n[j] = 1.f / g_norm[n0 + b_off + j];

    float* outp = g_Wt + ((size_t)b * HW + p0) * NC + n0 + b_off;
#pragma unroll
    for (int i = 0; i < 8; i++) {
        float w[8];
#pragma unroll
        for (int j = 0; j < 8; j++) {
            float x = acc[i][j] * inv_n[j];
            w[j] = 1.f / (1.f + expf(-x));
        }
        float* dst = outp + (size_t)(a_off + i) * NC;
        *(float4*)(dst)     = make_float4(w[0], w[1], w[2], w[3]);
        *(float4*)(dst + 4) = make_float4(w[4], w[5], w[6], w[7]);
    }
}

// ---------------------------------------------------------------------------
// K2: selective warp-affine fill + softmax over codes. 1 warp per pixel.
//   agent i = b % 2.  i>0 && masked[n]  -> bilinear sample of ego (b-1) weights
//   (fill condition provably equals zero_cond since sigmoid > 0 always).
// ---------------------------------------------------------------------------
__global__ __launch_bounds__(256) void warp_softmax_kernel() {
    const int warp = threadIdx.x >> 5, lane = threadIdx.x & 31;
    const int g = blockIdx.x * 8 + warp;            // 0 .. NB*HW-1
    const int b = g / HW;
    const int p = g - b * HW;

    const float* own = g_Wt + (size_t)g * NC;
    float4 o0 = *(const float4*)(own + lane * 4);
    float4 o1 = *(const float4*)(own + 128 + lane * 4);
    float v[8] = {o0.x, o0.y, o0.z, o0.w, o1.x, o1.y, o1.z, o1.w};

    if (b & 1) {   // agent > 0
        const int h = p / W_;
        const int w = p - h * W_;
        const float* th = g_theta[b];
        float gx = 2.f * (float)w / (float)(W_ - 1) - 1.f;
        float gy = 2.f * (float)h / (float)(H_ - 1) - 1.f;
        float cx2 = th[0] * gx + th[1] * gy + th[2];
        float cy2 = th[3] * gx + th[4] * gy + th[5];
        float x = (cx2 + 1.f) * (float)(W_ - 1) * 0.5f;
        float y = (cy2 + 1.f) * (float)(H_ - 1) * 0.5f;
        float x0f = floorf(x), y0f = floorf(y);
        int x0 = (int)x0f, y0 = (int)y0f;
        int x1 = x0 + 1,   y1 = y0 + 1;
        float fx = x - x0f, fy = y - y0f;
        bool vx0 = (x0 >= 0) && (x0 < W_), vx1 = (x1 >= 0) && (x1 < W_);
        bool vy0 = (y0 >= 0) && (y0 < H_), vy1 = (y1 >= 0) && (y1 < H_);
        float wa = (vx0 && vy0) ? (1.f - fx) * (1.f - fy) : 0.f;
        float wb = (vx1 && vy0) ? fx * (1.f - fy)         : 0.f;
        float wc = (vx0 && vy1) ? (1.f - fx) * fy         : 0.f;
        float wd = (vx1 && vy1) ? fx * fy                 : 0.f;
        int cx0 = min(max(x0, 0), W_ - 1), cx1 = min(max(x1, 0), W_ - 1);
        int cy0 = min(max(y0, 0), H_ - 1), cy1 = min(max(y1, 0), H_ - 1);

        const float* ego = g_Wt + (size_t)(b - 1) * HW * NC;
        const float* r00 = ego + (size_t)(cy0 * W_ + cx0) * NC;
        const float* r10 = ego + (size_t)(cy0 * W_ + cx1) * NC;
        const float* r01 = ego + (size_t)(cy1 * W_ + cx0) * NC;
        const float* r11 = ego + (size_t)(cy1 * W_ + cx1) * NC;

        int4 m0 = *(const int4*)&g_masked[lane * 4];
        int4 m1 = *(const int4*)&g_masked[128 + lane * 4];
        int mk[8] = {m0.x, m0.y, m0.z, m0.w, m1.x, m1.y, m1.z, m1.w};

#pragma unroll
        for (int half = 0; half < 2; half++) {
            int off = half * 128 + lane * 4;
            float4 a = *(const float4*)(r00 + off);
            float4 q = *(const float4*)(r10 + off);
            float4 c = *(const float4*)(r01 + off);
            float4 d = *(const float4*)(r11 + off);
            float wv[4] = {
                wa * a.x + wb * q.x + wc * c.x + wd * d.x,
                wa * a.y + wb * q.y + wc * c.y + wd * d.y,
                wa * a.z + wb * q.z + wc * c.z + wd * d.z,
                wa * a.w + wb * q.w + wc * c.w + wd * d.w};
#pragma unroll
            for (int j = 0; j < 4; j++)
                if (mk[half * 4 + j]) v[half * 4 + j] = wv[j];
        }
    }

    // softmax over the warp's 256 codes
    float m = v[0];
#pragma unroll
    for (int j = 1; j < 8; j++) m = fmaxf(m, v[j]);
#pragma unroll
    for (int o = 16; o > 0; o >>= 1) m = fmaxf(m, __shfl_xor_sync(0xffffffffu, m, o));
    float e[8]; float s = 0.f;
#pragma unroll
    for (int j = 0; j < 8; j++) { e[j] = expf(v[j] - m); s += e[j]; }
#pragma unroll
    for (int o = 16; o > 0; o >>= 1) s += __shfl_xor_sync(0xffffffffu, s, o);
    float inv = 1.f / s;

    float* dst = g_Ws + (size_t)g * NC;
    *(float4*)(dst + lane * 4)       = make_float4(e[0] * inv, e[1] * inv, e[2] * inv, e[3] * inv);
    *(float4*)(dst + 128 + lane * 4) = make_float4(e[4] * inv, e[5] * inv, e[6] * inv, e[7] * inv);
}

// ---------------------------------------------------------------------------
// GEMM2: out[b][c][p] = sum_n Ws[b][p][n] * cb[n][c]
// ---------------------------------------------------------------------------
__global__ __launch_bounds__(256) void gemm2_kernel(const float* __restrict__ cb,
                                                    float* __restrict__ out) {
    __shared__ float As[16][128];   // [n][p]
    __shared__ float Bs[16][128];   // [n][c]
    const int b  = blockIdx.z;
    const int p0 = blockIdx.x * 128;
    const int c0 = blockIdx.y * 128;
    const int tid  = threadIdx.x;
    const int lane = tid & 31, warp = tid >> 5;
    const int a_off = (warp >> 1) * 32 + (lane >> 3) * 8;   // p
    const int b_off = (warp & 1) * 64 + (lane & 7) * 8;     // c

    float acc[8][8] = {};

    const float* Abase = g_Ws + ((size_t)b * HW + p0) * NC;
    const int ap  = tid >> 2;          // 0..63
    const int an  = (tid & 3) * 4;
    const int brr = tid >> 5;          // 0..7
    const int bcc = (tid & 31) * 4;

    for (int k0 = 0; k0 < NC; k0 += 16) {
#pragma unroll
        for (int pass = 0; pass < 2; pass++) {
            int p = ap + pass * 64;
            float4 f = *(const float4*)(Abase + (size_t)p * NC + k0 + an);
            As[an + 0][p] = f.x; As[an + 1][p] = f.y;
            As[an + 2][p] = f.z; As[an + 3][p] = f.w;
        }
#pragma unroll
        for (int pass = 0; pass < 2; pass++) {
            int r = brr + pass * 8;
            *(float4*)&Bs[r][bcc] = *(const float4*)(cb + (size_t)(k0 + r) * CD + c0 + bcc);
        }
        __syncthreads();
#pragma unroll
        for (int kc = 0; kc < 16; kc++) {
            float4 a0 = *(const float4*)&As[kc][a_off];
            float4 a1 = *(const float4*)&As[kc][a_off + 4];
            float4 b0 = *(const float4*)&Bs[kc][b_off];
            float4 b1 = *(const float4*)&Bs[kc][b_off + 4];
            float ar[8] = {a0.x, a0.y, a0.z, a0.w, a1.x, a1.y, a1.z, a1.w};
            float br[8] = {b0.x, b0.y, b0.z, b0.w, b1.x, b1.y, b1.z, b1.w};
#pragma unroll
            for (int i = 0; i < 8; i++)
#pragma unroll
                for (int j = 0; j < 8; j++)
                    acc[i][j] = fmaf(ar[i], br[j], acc[i][j]);
        }
        __syncthreads();
    }

#pragma unroll
    for (int j = 0; j < 8; j++) {
        float* dst = out + ((size_t)b * CD + c0 + b_off + j) * HW + p0 + a_off;
        *(float4*)dst       = make_float4(acc[0][j], acc[1][j], acc[2][j], acc[3][j]);
        *(float4*)(dst + 4) = make_float4(acc[4][j], acc[5][j], acc[6][j], acc[7][j]);
    }
}

// ---------------------------------------------------------------------------
extern "C" void kernel_launch(void* const* d_in, const int* in_sizes, int n_in,
                              void* d_out, int out_size) {
    (void)in_sizes; (void)n_in; (void)out_size;
    const float* feat = (const float*)d_in[0];   // [8,256,96,192]
    const float* cb   = (const float*)d_in[1];   // [256,256]
    const float* pub  = (const float*)d_in[2];   // [256,256]
    const float* aff  = (const float*)d_in[3];   // [4,2,2,2,3]
    float* out = (float*)d_out;                  // [8,256,96,192]

    setup_kernel<<<NC, 256>>>(cb, pub, aff);

    dim3 g1(HW / 128, NC / 128, NB);
    gemm1_kernel<<<g1, 256>>>(feat, cb);

    warp_softmax_kernel<<<NB * HW / 8, 256>>>();

    dim3 g2(HW / 128, CD / 128, NB);
    gemm2_kernel<<<g2, 256>>>(cb, out);
}

// round 3
// speedup vs baseline: 1.3336x; 1.3336x over previous
#include <cuda_runtime.h>
#include <mma.h>
#include <math.h>

using namespace nvcuda;

#define B_   4
#define N_   2
#define NB   8          // B_*N_ flattened images
#define NC   256        // codes
#define CD   256        // channels
#define H_   96
#define W_   192
#define HW   (H_*W_)    // 18432

// Scratch (static __device__ per harness rules; .bss, not stored in binary)
__device__ float g_Wt[(size_t)NB * HW * NC];   // sigmoid weights, layout [b][p][n]
__device__ float g_Ws[(size_t)NB * HW * NC];   // softmaxed weights, layout [b][p][n]
__device__ float g_cbT[NC * NC];               // cbT[c][n] = cb[n][c] / norm2[n]
__device__ float g_norm[NC];
__device__ int   g_masked[NC];
__device__ float g_theta[NB][6];

__device__ __forceinline__ float to_tf32(float x) {
    float r;
    asm("cvt.rna.tf32.f32 %0, %1;" : "=f"(r) : "f"(x));
    return r;
}

// ---------------------------------------------------------------------------
// Setup: per-code norm^2, cosine mask vs codebook_pub, theta copy.
// ---------------------------------------------------------------------------
__global__ __launch_bounds__(256) void setup_kernel(const float* __restrict__ cb,
                                                    const float* __restrict__ pub,
                                                    const float* __restrict__ aff) {
    __shared__ float red[256];
    const int n = blockIdx.x, t = threadIdx.x;

    float v = cb[n * CD + t];
    red[t] = v * v;
    __syncthreads();
    for (int s = 128; s > 0; s >>= 1) { if (t < s) red[t] += red[t + s]; __syncthreads(); }
    const float cbn2 = red[0];
    __syncthreads();

    const float* cr = cb + n * CD;
    const float* pr = pub + t * CD;
    float dot = 0.f, pn2 = 0.f;
#pragma unroll 8
    for (int c = 0; c < CD; c++) {
        float pv = pr[c];
        dot = fmaf(cr[c], pv, dot);
        pn2 = fmaf(pv, pv, pn2);
    }
    red[t] = dot * rsqrtf(cbn2 * pn2);
    __syncthreads();
    for (int s = 128; s > 0; s >>= 1) { if (t < s) red[t] = fmaxf(red[t], red[t + s]); __syncthreads(); }

    if (t == 0) {
        g_masked[n] = (red[0] <= 0.5f) ? 1 : 0;
        g_norm[n]   = cbn2;
    }
    if (n == 0 && t < NB * 6) g_theta[t / 6][t % 6] = aff[(t / 6) * 12 + (t % 6)];
}

// cbT[c][n] = cb[n][c] / norm2[n]   (tiny; cb fits L2)
__global__ __launch_bounds__(256) void cbt_kernel(const float* __restrict__ cb) {
    const int c = blockIdx.x, n = threadIdx.x;
    g_cbT[c * NC + n] = cb[n * CD + c] / g_norm[n];
}

// ---------------------------------------------------------------------------
// GEMM1 (tf32 wmma): Wt[p][n] = sigmoid( sum_c feat[c][p] * cbT[c][n] )
// Block tile 128p x 128n, 8 warps (2m x 4n), warp tile 64x32, K chunk 32.
// ---------------------------------------------------------------------------
__global__ __launch_bounds__(256) void gemm1_wmma(const float* __restrict__ feat) {
    __shared__ float As[32][136];   // [k=c][p]
    __shared__ float Bs[32][136];   // [k=c][n]
    const int b  = blockIdx.z;
    const int p0 = blockIdx.x * 128;
    const int n0 = blockIdx.y * 128;
    const int tid  = threadIdx.x;
    const int warp = tid >> 5;
    const int wm = warp >> 2;       // 0..1 -> p offset wm*64
    const int wn = warp & 3;        // 0..3 -> n offset wn*32

    wmma::fragment<wmma::accumulator, 16, 16, 8, float> acc[4][2];
#pragma unroll
    for (int i = 0; i < 4; i++)
#pragma unroll
        for (int j = 0; j < 2; j++) wmma::fill_fragment(acc[i][j], 0.0f);

    const float* fbase = feat + (size_t)b * CD * HW + p0;

    for (int k0 = 0; k0 < CD; k0 += 32) {
#pragma unroll
        for (int i = 0; i < 4; i++) {
            int idx = tid + i * 256;
            int r = idx >> 5, c4 = (idx & 31) * 4;
            float4 f = *(const float4*)(fbase + (size_t)(k0 + r) * HW + c4);
            f.x = to_tf32(f.x); f.y = to_tf32(f.y); f.z = to_tf32(f.z); f.w = to_tf32(f.w);
            *(float4*)&As[r][c4] = f;
            float4 g = *(const float4*)(g_cbT + (k0 + r) * NC + n0 + c4);
            g.x = to_tf32(g.x); g.y = to_tf32(g.y); g.z = to_tf32(g.z); g.w = to_tf32(g.w);
            *(float4*)&Bs[r][c4] = g;
        }
        __syncthreads();
#pragma unroll
        for (int kk = 0; kk < 4; kk++) {
            wmma::fragment<wmma::matrix_a, 16, 16, 8, wmma::precision::tf32, wmma::col_major> a[4];
            wmma::fragment<wmma::matrix_b, 16, 16, 8, wmma::precision::tf32, wmma::row_major> bb[2];
#pragma unroll
            for (int i = 0; i < 4; i++)
                wmma::load_matrix_sync(a[i], &As[kk * 8][wm * 64 + i * 16], 136);
#pragma unroll
            for (int j = 0; j < 2; j++)
                wmma::load_matrix_sync(bb[j], &Bs[kk * 8][wn * 32 + j * 16], 136);
#pragma unroll
            for (int i = 0; i < 4; i++)
#pragma unroll
                for (int j = 0; j < 2; j++)
                    wmma::mma_sync(acc[i][j], a[i], bb[j], acc[i][j]);
        }
        __syncthreads();
    }

    // elementwise sigmoid on fragments (uniform op — mapping-independent), store
    float* outbase = g_Wt + ((size_t)b * HW + p0) * NC + n0;
#pragma unroll
    for (int i = 0; i < 4; i++)
#pragma unroll
        for (int j = 0; j < 2; j++) {
#pragma unroll
            for (int e = 0; e < acc[i][j].num_elements; e++) {
                float x = acc[i][j].x[e];
                acc[i][j].x[e] = 1.0f / (1.0f + __expf(-x));
            }
            wmma::store_matrix_sync(outbase + (size_t)(wm * 64 + i * 16) * NC + wn * 32 + j * 16,
                                    acc[i][j], NC, wmma::mem_row_major);
        }
}

// ---------------------------------------------------------------------------
// K2: selective warp-affine fill + softmax over codes. 1 warp per pixel.
// ---------------------------------------------------------------------------
__global__ __launch_bounds__(256) void warp_softmax_kernel() {
    const int warp = threadIdx.x >> 5, lane = threadIdx.x & 31;
    const int g = blockIdx.x * 8 + warp;
    const int b = g / HW;
    const int p = g - b * HW;

    const float* own = g_Wt + (size_t)g * NC;
    float4 o0 = *(const float4*)(own + lane * 4);
    float4 o1 = *(const float4*)(own + 128 + lane * 4);
    float v[8] = {o0.x, o0.y, o0.z, o0.w, o1.x, o1.y, o1.z, o1.w};

    if (b & 1) {   // agent > 0
        const int h = p / W_;
        const int w = p - h * W_;
        const float* th = g_theta[b];
        float gx = 2.f * (float)w / (float)(W_ - 1) - 1.f;
        float gy = 2.f * (float)h / (float)(H_ - 1) - 1.f;
        float cx2 = th[0] * gx + th[1] * gy + th[2];
        float cy2 = th[3] * gx + th[4] * gy + th[5];
        float x = (cx2 + 1.f) * (float)(W_ - 1) * 0.5f;
        float y = (cy2 + 1.f) * (float)(H_ - 1) * 0.5f;
        float x0f = floorf(x), y0f = floorf(y);
        int x0 = (int)x0f, y0 = (int)y0f;
        int x1 = x0 + 1,   y1 = y0 + 1;
        float fx = x - x0f, fy = y - y0f;
        bool vx0 = (x0 >= 0) && (x0 < W_), vx1 = (x1 >= 0) && (x1 < W_);
        bool vy0 = (y0 >= 0) && (y0 < H_), vy1 = (y1 >= 0) && (y1 < H_);
        float wa = (vx0 && vy0) ? (1.f - fx) * (1.f - fy) : 0.f;
        float wb = (vx1 && vy0) ? fx * (1.f - fy)         : 0.f;
        float wc = (vx0 && vy1) ? (1.f - fx) * fy         : 0.f;
        float wd = (vx1 && vy1) ? fx * fy                 : 0.f;
        int cx0 = min(max(x0, 0), W_ - 1), cx1 = min(max(x1, 0), W_ - 1);
        int cy0 = min(max(y0, 0), H_ - 1), cy1 = min(max(y1, 0), H_ - 1);

        const float* ego = g_Wt + (size_t)(b - 1) * HW * NC;
        const float* r00 = ego + (size_t)(cy0 * W_ + cx0) * NC;
        const float* r10 = ego + (size_t)(cy0 * W_ + cx1) * NC;
        const float* r01 = ego + (size_t)(cy1 * W_ + cx0) * NC;
        const float* r11 = ego + (size_t)(cy1 * W_ + cx1) * NC;

        int4 m0 = *(const int4*)&g_masked[lane * 4];
        int4 m1 = *(const int4*)&g_masked[128 + lane * 4];
        int mk[8] = {m0.x, m0.y, m0.z, m0.w, m1.x, m1.y, m1.z, m1.w};

#pragma unroll
        for (int half = 0; half < 2; half++) {
            int off = half * 128 + lane * 4;
            float4 a = *(const float4*)(r00 + off);
            float4 q = *(const float4*)(r10 + off);
            float4 c = *(const float4*)(r01 + off);
            float4 d = *(const float4*)(r11 + off);
            float wv[4] = {
                wa * a.x + wb * q.x + wc * c.x + wd * d.x,
                wa * a.y + wb * q.y + wc * c.y + wd * d.y,
                wa * a.z + wb * q.z + wc * c.z + wd * d.z,
                wa * a.w + wb * q.w + wc * c.w + wd * d.w};
#pragma unroll
            for (int j = 0; j < 4; j++)
                if (mk[half * 4 + j]) v[half * 4 + j] = wv[j];
        }
    }

    float m = v[0];
#pragma unroll
    for (int j = 1; j < 8; j++) m = fmaxf(m, v[j]);
#pragma unroll
    for (int o = 16; o > 0; o >>= 1) m = fmaxf(m, __shfl_xor_sync(0xffffffffu, m, o));
    float e[8]; float s = 0.f;
#pragma unroll
    for (int j = 0; j < 8; j++) { e[j] = expf(v[j] - m); s += e[j]; }
#pragma unroll
    for (int o = 16; o > 0; o >>= 1) s += __shfl_xor_sync(0xffffffffu, s, o);
    float inv = 1.f / s;

    float* dst = g_Ws + (size_t)g * NC;
    *(float4*)(dst + lane * 4)       = make_float4(e[0] * inv, e[1] * inv, e[2] * inv, e[3] * inv);
    *(float4*)(dst + 128 + lane * 4) = make_float4(e[4] * inv, e[5] * inv, e[6] * inv, e[7] * inv);
}

// ---------------------------------------------------------------------------
// GEMM2 (tf32 wmma): out[c][p] = sum_n Ws[p][n] * cb[n][c]
// Block tile 128p x 128c, 8 warps (2m x 4n), warp tile 64x32, K chunk 32.
// Accumulator (p,c) stored col-major -> out[c][p] directly.
// ---------------------------------------------------------------------------
__global__ __launch_bounds__(256) void gemm2_wmma(const float* __restrict__ cb,
                                                  float* __restrict__ out) {
    __shared__ float As[128][40];   // [p][k=n chunk], pad 40
    __shared__ float Bs[32][136];   // [k=n][c]
    const int b  = blockIdx.z;
    const int p0 = blockIdx.x * 128;
    const int c0 = blockIdx.y * 128;
    const int tid  = threadIdx.x;
    const int warp = tid >> 5;
    const int wm = warp >> 2;       // p offset wm*64
    const int wn = warp & 3;        // c offset wn*32

    wmma::fragment<wmma::accumulator, 16, 16, 8, float> acc[4][2];
#pragma unroll
    for (int i = 0; i < 4; i++)
#pragma unroll
        for (int j = 0; j < 2; j++) wmma::fill_fragment(acc[i][j], 0.0f);

    const float* Abase = g_Ws + ((size_t)b * HW + p0) * NC;

    for (int k0 = 0; k0 < NC; k0 += 32) {
#pragma unroll
        for (int i = 0; i < 4; i++) {
            int idx = tid + i * 256;
            int p = idx >> 3, c4 = (idx & 7) * 4;      // 128 rows x 8 float4
            float4 f = *(const float4*)(Abase + (size_t)p * NC + k0 + c4);
            f.x = to_tf32(f.x); f.y = to_tf32(f.y); f.z = to_tf32(f.z); f.w = to_tf32(f.w);
            *(float4*)&As[p][c4] = f;
        }
#pragma unroll
        for (int i = 0; i < 4; i++) {
            int idx = tid + i * 256;
            int r = idx >> 5, c4 = (idx & 31) * 4;
            float4 g = *(const float4*)(cb + (size_t)(k0 + r) * CD + c0 + c4);
            g.x = to_tf32(g.x); g.y = to_tf32(g.y); g.z = to_tf32(g.z); g.w = to_tf32(g.w);
            *(float4*)&Bs[r][c4] = g;
        }
        __syncthreads();
#pragma unroll
        for (int kk = 0; kk < 4; kk++) {
            wmma::fragment<wmma::matrix_a, 16, 16, 8, wmma::precision::tf32, wmma::row_major> a[4];
            wmma::fragment<wmma::matrix_b, 16, 16, 8, wmma::precision::tf32, wmma::row_major> bb[2];
#pragma unroll
            for (int i = 0; i < 4; i++)
                wmma::load_matrix_sync(a[i], &As[wm * 64 + i * 16][kk * 8], 40);
#pragma unroll
            for (int j = 0; j < 2; j++)
                wmma::load_matrix_sync(bb[j], &Bs[kk * 8][wn * 32 + j * 16], 136);
#pragma unroll
            for (int i = 0; i < 4; i++)
#pragma unroll
                for (int j = 0; j < 2; j++)
                    wmma::mma_sync(acc[i][j], a[i], bb[j], acc[i][j]);
        }
        __syncthreads();
    }

    float* obase = out + (size_t)b * CD * HW;
#pragma unroll
    for (int i = 0; i < 4; i++)
#pragma unroll
        for (int j = 0; j < 2; j++) {
            int pp = p0 + wm * 64 + i * 16;
            int cc = c0 + wn * 32 + j * 16;
            wmma::store_matrix_sync(obase + (size_t)cc * HW + pp, acc[i][j], HW,
                                    wmma::mem_col_major);
        }
}

// ---------------------------------------------------------------------------
extern "C" void kernel_launch(void* const* d_in, const int* in_sizes, int n_in,
                              void* d_out, int out_size) {
    (void)in_sizes; (void)n_in; (void)out_size;
    const float* feat = (const float*)d_in[0];   // [8,256,96,192]
    const float* cb   = (const float*)d_in[1];   // [256,256]
    const float* pub  = (const float*)d_in[2];   // [256,256]
    const float* aff  = (const float*)d_in[3];   // [4,2,2,2,3]
    float* out = (float*)d_out;                  // [8,256,96,192]

    setup_kernel<<<NC, 256>>>(cb, pub, aff);
    cbt_kernel<<<NC, 256>>>(cb);

    dim3 g1(HW / 128, NC / 128, NB);
    gemm1_wmma<<<g1, 256>>>(feat);

    warp_softmax_kernel<<<NB * HW / 8, 256>>>();

    dim3 g2(HW / 128, CD / 128, NB);
    gemm2_wmma<<<g2, 256>>>(cb, out);
}

// round 7
// speedup vs baseline: 2.9312x; 2.1980x over previous
#include <cuda_runtime.h>
#include <cuda_fp16.h>
#include <math.h>
#include <stdint.h>

#define B_   4
#define NB   8          // flattened images
#define NC   256        // codes
#define CD   256        // channels
#define H_   96
#define W_   192
#define HW   (H_*W_)    // 18432
#define NTILE 144       // HW/128

// ---------------- global scratch (.bss) ----------------
__device__ __align__(256) float  g_Wt[(size_t)NB * HW * NC];    // sigmoid weights [b][p][n] fp32
__device__ __align__(256) __half g_WsTh[(size_t)NB * HW * NC];  // softmax weights, tile-swizzled fp16
__device__ __align__(256) __half g_B1h[NC * CD];                // cb[n][c]/norm2[n], tiled
__device__ __align__(256) __half g_B2h[NC * CD];                // cb as rows c, k=n, tiled
__device__ float g_norm[NC];
__device__ int   g_masked[NC];
__device__ float g_theta[NB][6];

// ---------------- helpers ----------------
__device__ __forceinline__ uint32_t smem_u32(const void* p) {
    uint32_t a;
    asm("{ .reg .u64 t; cvta.to.shared.u64 t, %1; cvt.u32.u64 %0, t; }" : "=r"(a) : "l"(p));
    return a;
}

// SW128 swizzle: byte offset within a 128-row x 128-byte tile
__device__ __forceinline__ int swz(int row, int bytecol) {
    return row * 128 + (bytecol ^ ((row & 7) << 4));
}

#define LDSM4(d0, d1, d2, d3, a) \
    asm volatile("ldmatrix.sync.aligned.m8n8.x4.shared.b16 {%0,%1,%2,%3}, [%4];" \
                 : "=r"(d0), "=r"(d1), "=r"(d2), "=r"(d3) : "r"(a))

#define MMA16816(d, a0, a1, a2, a3, b0, b1) \
    asm volatile("mma.sync.aligned.m16n8k16.row.col.f32.f16.f16.f32 " \
                 "{%0,%1,%2,%3}, {%4,%5,%6,%7}, {%8,%9}, {%0,%1,%2,%3};" \
                 : "+f"((d)[0]), "+f"((d)[1]), "+f"((d)[2]), "+f"((d)[3]) \
                 : "r"(a0), "r"(a1), "r"(a2), "r"(a3), "r"(b0), "r"(b1))

#define CP16(dst, src) \
    asm volatile("cp.async.cg.shared.global [%0], [%1], 16;" :: "r"(dst), "l"(src))
#define CP_COMMIT() asm volatile("cp.async.commit_group;" ::: "memory")
#define CP_WAIT(n)  asm volatile("cp.async.wait_group %0;" :: "n"(n) : "memory")

// ---------------------------------------------------------------------------
// Setup: per-code norm^2, cosine mask, theta copy.
// ---------------------------------------------------------------------------
__global__ __launch_bounds__(256) void setup_kernel(const float* __restrict__ cb,
                                                    const float* __restrict__ pub,
                                                    const float* __restrict__ aff) {
    __shared__ float red[256];
    const int n = blockIdx.x, t = threadIdx.x;

    float v = cb[n * CD + t];
    red[t] = v * v;
    __syncthreads();
    for (int s = 128; s > 0; s >>= 1) { if (t < s) red[t] += red[t + s]; __syncthreads(); }
    const float cbn2 = red[0];
    __syncthreads();

    const float* cr = cb + n * CD;
    const float* pr = pub + t * CD;
    float dot = 0.f, pn2 = 0.f;
#pragma unroll 8
    for (int c = 0; c < CD; c++) {
        float pv = pr[c];
        dot = fmaf(cr[c], pv, dot);
        pn2 = fmaf(pv, pv, pn2);
    }
    red[t] = dot * rsqrtf(cbn2 * pn2);
    __syncthreads();
    for (int s = 128; s > 0; s >>= 1) { if (t < s) red[t] = fmaxf(red[t], red[t + s]); __syncthreads(); }

    if (t == 0) {
        g_masked[n] = (red[0] <= 0.5f) ? 1 : 0;
        g_norm[n]   = cbn2;
    }
    if (n == 0 && t < NB * 6) g_theta[t / 6][t % 6] = aff[(t / 6) * 12 + (t % 6)];
}

// ---------------------------------------------------------------------------
// Prep: fp16 pre-swizzled operands.
//   B1: rows n, k=c contiguous, tiles [nblk][stage][128rows x 64k SW128]
//   B2: rows c, k=n contiguous, tiles [cblk][stage][...]
// ---------------------------------------------------------------------------
__global__ __launch_bounds__(256) void prep_kernel(const float* __restrict__ cb) {
    const int r = blockIdx.x, t = threadIdx.x;
    const float inv = 1.f / g_norm[r];

    {   // B1: row n=r, k=c=t
        float x = cb[r * CD + t] * inv;
        int e = (r >> 7) * 32768 + (t >> 6) * 8192 + (swz(r & 127, 2 * (t & 63)) >> 1);
        g_B1h[e] = __float2half(x);
    }
    {   // B2: row c=r, k=n=t
        float x = cb[t * CD + r];
        int e = (r >> 7) * 32768 + (t >> 6) * 8192 + (swz(r & 127, 2 * (t & 63)) >> 1);
        g_B2h[e] = __float2half(x);
    }
}

// ---------------------------------------------------------------------------
// GEMM1: Wt[p][n] = sigmoid( sum_c feat[c][p] * cb[n][c] / norm2[n] )
// CTA: 128p x 128n; grid (144, 2, 8). B fully prefetched via cp.async (4 stages),
// A (feat transpose->fp16) register-prefetch double buffered.
// smem: B 4x16KB @0, A 2x16KB @65536.
// ---------------------------------------------------------------------------
__global__ __launch_bounds__(256) void gemm1_mma(const float* __restrict__ feat) {
    extern __shared__ char smem_raw[];
    uint32_t sb0 = smem_u32(smem_raw);
    uint32_t base = (sb0 + 127u) & ~127u;
    char* smem = smem_raw + (base - sb0);

    const int tid = threadIdx.x;
    const int lane = tid & 31, warp = tid >> 5;
    const int wm = warp >> 2;        // 0..1 -> m offset wm*64
    const int wn = warp & 3;         // 0..3 -> n offset wn*32
    const int b  = blockIdx.z;
    const int p0 = blockIdx.x * 128;
    const int ny = blockIdx.y;       // n block 0/1

    // issue all B stage copies (4 groups)
    {
        const char* src = (const char*)(g_B1h + ny * 32768);
#pragma unroll
        for (int s = 0; s < 4; s++) {
#pragma unroll
            for (int k = 0; k < 4; k++) {
                int idx = tid + k * 256;
                CP16(base + s * 16384 + idx * 16, src + s * 16384 + idx * 16);
            }
            CP_COMMIT();
        }
    }

    // ldmatrix per-lane address precompute
    int rA_off[4], xmA[4];
#pragma unroll
    for (int mt = 0; mt < 4; mt++) {
        int r = wm * 64 + mt * 16 + (lane & 15);
        rA_off[mt] = r * 128;
        xmA[mt] = (r & 7) << 4;
    }
    const int cb0A = (lane >> 4) << 4;
    int rB_off[2], xmB[2];
#pragma unroll
    for (int g = 0; g < 2; g++) {
        int r = wn * 32 + g * 16 + ((lane >> 4) << 3) + (lane & 7);
        rB_off[g] = r * 128;
        xmB[g] = (r & 7) << 4;
    }
    const int cb0B = ((lane >> 3) & 1) << 4;

    float acc[4][4][4] = {};

    const float* fbase = feat + (size_t)b * CD * HW + p0;
    float ar[32];

    // prologue: load + store stage 0 A
#pragma unroll
    for (int i = 0; i < 16; i++) {
        int idx = tid + i * 256;
        int cp = idx >> 7, p = idx & 127;
        ar[2 * i]     = fbase[(size_t)(2 * cp) * HW + p];
        ar[2 * i + 1] = fbase[(size_t)(2 * cp + 1) * HW + p];
    }
    {
        char* A0 = smem + 65536;
#pragma unroll
        for (int i = 0; i < 16; i++) {
            int idx = tid + i * 256;
            int cp = idx >> 7, p = idx & 127;
            *(__half2*)(A0 + swz(p, 4 * cp)) =
                __floats2half2_rn(ar[2 * i], ar[2 * i + 1]);
        }
    }

    for (int s = 0; s < 4; s++) {
        // prefetch next A stage into regs
        if (s < 3) {
            const float* fs = fbase + (size_t)(s + 1) * 64 * HW;
#pragma unroll
            for (int i = 0; i < 16; i++) {
                int idx = tid + i * 256;
                int cp = idx >> 7, p = idx & 127;
                ar[2 * i]     = fs[(size_t)(2 * cp) * HW + p];
                ar[2 * i + 1] = fs[(size_t)(2 * cp + 1) * HW + p];
            }
        }
        // wait for B stage s
        if (s == 0) CP_WAIT(3);
        else if (s == 1) CP_WAIT(2);
        else if (s == 2) CP_WAIT(1);
        else CP_WAIT(0);
        __syncthreads();

        const uint32_t Abuf = base + 65536 + (s & 1) * 16384;
        const uint32_t Bst  = base + s * 16384;
#pragma unroll
        for (int ks = 0; ks < 4; ks++) {
            uint32_t a[4][4], bf[4][2];
#pragma unroll
            for (int mt = 0; mt < 4; mt++)
                LDSM4(a[mt][0], a[mt][1], a[mt][2], a[mt][3],
                      Abuf + rA_off[mt] + ((ks * 32 + cb0A) ^ xmA[mt]));
#pragma unroll
            for (int g = 0; g < 2; g++) {
                uint32_t r0, r1, r2, r3;
                LDSM4(r0, r1, r2, r3, Bst + rB_off[g] + ((ks * 32 + cb0B) ^ xmB[g]));
                bf[2 * g][0] = r0; bf[2 * g][1] = r1;
                bf[2 * g + 1][0] = r2; bf[2 * g + 1][1] = r3;
            }
#pragma unroll
            for (int mt = 0; mt < 4; mt++)
#pragma unroll
                for (int nt = 0; nt < 4; nt++)
                    MMA16816(acc[mt][nt], a[mt][0], a[mt][1], a[mt][2], a[mt][3],
                             bf[nt][0], bf[nt][1]);
        }

        if (s < 3) {
            char* An = smem + 65536 + ((s + 1) & 1) * 16384;
#pragma unroll
            for (int i = 0; i < 16; i++) {
                int idx = tid + i * 256;
                int cp = idx >> 7, p = idx & 127;
                *(__half2*)(An + swz(p, 4 * cp)) =
                    __floats2half2_rn(ar[2 * i], ar[2 * i + 1]);
            }
        }
        __syncthreads();
    }

    // epilogue: sigmoid + direct STG (rows p, contiguous n)
    float* outb = g_Wt + ((size_t)b * HW + p0) * NC + ny * 128;
#pragma unroll
    for (int mt = 0; mt < 4; mt++) {
        int pr = wm * 64 + mt * 16 + (lane >> 2);
#pragma unroll
        for (int nt = 0; nt < 4; nt++) {
            int nc = wn * 32 + nt * 8 + (lane & 3) * 2;
            float* d0 = outb + (size_t)pr * NC + nc;
            float* d1 = outb + (size_t)(pr + 8) * NC + nc;
            float2 v0 = make_float2(1.f / (1.f + __expf(-acc[mt][nt][0])),
                                    1.f / (1.f + __expf(-acc[mt][nt][1])));
            float2 v1 = make_float2(1.f / (1.f + __expf(-acc[mt][nt][2])),
                                    1.f / (1.f + __expf(-acc[mt][nt][3])));
            *(float2*)d0 = v0;
            *(float2*)d1 = v1;
        }
    }
}

// ---------------------------------------------------------------------------
// K2: selective warp-affine fill + softmax. 1 warp/pixel.
// Writes tile-swizzled fp16 (GEMM2 A operand) directly.
// ---------------------------------------------------------------------------
__global__ __launch_bounds__(256) void warp_softmax_kernel() {
    const int warp = threadIdx.x >> 5, lane = threadIdx.x & 31;
    const int g = blockIdx.x * 8 + warp;
    const int b = g / HW;
    const int p = g - b * HW;

    const float* own = g_Wt + (size_t)g * NC;
    float4 o0 = *(const float4*)(own + lane * 4);
    float4 o1 = *(const float4*)(own + 128 + lane * 4);
    float v[8] = {o0.x, o0.y, o0.z, o0.w, o1.x, o1.y, o1.z, o1.w};

    if (b & 1) {   // agent > 0
        const int h = p / W_;
        const int w = p - h * W_;
        const float* th = g_theta[b];
        float gx = 2.f * (float)w / (float)(W_ - 1) - 1.f;
        float gy = 2.f * (float)h / (float)(H_ - 1) - 1.f;
        float cx2 = th[0] * gx + th[1] * gy + th[2];
        float cy2 = th[3] * gx + th[4] * gy + th[5];
        float x = (cx2 + 1.f) * (float)(W_ - 1) * 0.5f;
        float y = (cy2 + 1.f) * (float)(H_ - 1) * 0.5f;
        float x0f = floorf(x), y0f = floorf(y);
        int x0 = (int)x0f, y0 = (int)y0f;
        int x1 = x0 + 1,   y1 = y0 + 1;
        float fx = x - x0f, fy = y - y0f;
        bool vx0 = (x0 >= 0) && (x0 < W_), vx1 = (x1 >= 0) && (x1 < W_);
        bool vy0 = (y0 >= 0) && (y0 < H_), vy1 = (y1 >= 0) && (y1 < H_);
        float wa = (vx0 && vy0) ? (1.f - fx) * (1.f - fy) : 0.f;
        float wb = (vx1 && vy0) ? fx * (1.f - fy)         : 0.f;
        float wc = (vx0 && vy1) ? (1.f - fx) * fy         : 0.f;
        float wd = (vx1 && vy1) ? fx * fy                 : 0.f;
        int cx0 = min(max(x0, 0), W_ - 1), cx1 = min(max(x1, 0), W_ - 1);
        int cy0 = min(max(y0, 0), H_ - 1), cy1 = min(max(y1, 0), H_ - 1);

        const float* ego = g_Wt + (size_t)(b - 1) * HW * NC;
        const float* r00 = ego + (size_t)(cy0 * W_ + cx0) * NC;
        const float* r10 = ego + (size_t)(cy0 * W_ + cx1) * NC;
        const float* r01 = ego + (size_t)(cy1 * W_ + cx0) * NC;
        const float* r11 = ego + (size_t)(cy1 * W_ + cx1) * NC;

        int4 m0 = *(const int4*)&g_masked[lane * 4];
        int4 m1 = *(const int4*)&g_masked[128 + lane * 4];
        int mk[8] = {m0.x, m0.y, m0.z, m0.w, m1.x, m1.y, m1.z, m1.w};

#pragma unroll
        for (int half = 0; half < 2; half++) {
            int off = half * 128 + lane * 4;
            float4 a = *(const float4*)(r00 + off);
            float4 q = *(const float4*)(r10 + off);
            float4 c = *(const float4*)(r01 + off);
            float4 d = *(const float4*)(r11 + off);
            float wv[4] = {
                wa * a.x + wb * q.x + wc * c.x + wd * d.x,
                wa * a.y + wb * q.y + wc * c.y + wd * d.y,
                wa * a.z + wb * q.z + wc * c.z + wd * d.z,
                wa * a.w + wb * q.w + wc * c.w + wd * d.w};
#pragma unroll
            for (int j = 0; j < 4; j++)
                if (mk[half * 4 + j]) v[half * 4 + j] = wv[j];
        }
    }

    float m = v[0];
#pragma unroll
    for (int j = 1; j < 8; j++) m = fmaxf(m, v[j]);
#pragma unroll
    for (int o = 16; o > 0; o >>= 1) m = fmaxf(m, __shfl_xor_sync(0xffffffffu, m, o));
    float e[8]; float s = 0.f;
#pragma unroll
    for (int j = 0; j < 8; j++) { e[j] = expf(v[j] - m); s += e[j]; }
#pragma unroll
    for (int o = 16; o > 0; o >>= 1) s += __shfl_xor_sync(0xffffffffu, s, o);
    float inv = 1.f / s;

    // write tile-swizzled fp16 (GEMM2 A layout)
    const int pl = p & 127;
    const size_t tb = (size_t)(b * NTILE + (p >> 7)) * 32768;
#pragma unroll
    for (int grp = 0; grp < 2; grp++) {
        int n0 = grp * 128 + lane * 4;
        int st = n0 >> 6, nl = n0 & 63;
        size_t eidx = tb + (size_t)st * 8192 + (size_t)(swz(pl, 2 * nl) >> 1);
        *(__half2*)(g_WsTh + eidx)     = __floats2half2_rn(e[grp * 4 + 0] * inv, e[grp * 4 + 1] * inv);
        *(__half2*)(g_WsTh + eidx + 2) = __floats2half2_rn(e[grp * 4 + 2] * inv, e[grp * 4 + 3] * inv);
    }
}

// ---------------------------------------------------------------------------
// GEMM2: out[c][p] = sum_n Ws[p][n] * cb[n][c]
// CTA: 128p x 128c; grid (144, 2, 8). Both operands cp.async double-buffered.
// smem: stage buf s: A @ (s&1)*32768, B @ +16384. Epilogue E (128x132 f32) @0.
// ---------------------------------------------------------------------------
__global__ __launch_bounds__(256) void gemm2_mma(float* __restrict__ out) {
    extern __shared__ char smem_raw[];
    uint32_t sb0 = smem_u32(smem_raw);
    uint32_t base = (sb0 + 127u) & ~127u;
    char* smem = smem_raw + (base - sb0);

    const int tid = threadIdx.x;
    const int lane = tid & 31, warp = tid >> 5;
    const int wm = warp >> 2;
    const int wn = warp & 3;
    const int b  = blockIdx.z;
    const int p0 = blockIdx.x * 128;
    const int cy = blockIdx.y;

    const char* srcA = (const char*)(g_WsTh + (size_t)(b * NTILE + blockIdx.x) * 32768);
    const char* srcB = (const char*)(g_B2h + cy * 32768);

    auto issue = [&](int s) {
        uint32_t dA = base + (s & 1) * 32768;
        uint32_t dB = dA + 16384;
#pragma unroll
        for (int k = 0; k < 4; k++) {
            int idx = tid + k * 256;
            CP16(dA + idx * 16, srcA + (size_t)s * 16384 + idx * 16);
        }
#pragma unroll
        for (int k = 0; k < 4; k++) {
            int idx = tid + k * 256;
            CP16(dB + idx * 16, srcB + (size_t)s * 16384 + idx * 16);
        }
        CP_COMMIT();
    };

    issue(0);
    issue(1);

    int rA_off[4], xmA[4];
#pragma unroll
    for (int mt = 0; mt < 4; mt++) {
        int r = wm * 64 + mt * 16 + (lane & 15);
        rA_off[mt] = r * 128;
        xmA[mt] = (r & 7) << 4;
    }
    const int cb0A = (lane >> 4) << 4;
    int rB_off[2], xmB[2];
#pragma unroll
    for (int g = 0; g < 2; g++) {
        int r = wn * 32 + g * 16 + ((lane >> 4) << 3) + (lane & 7);
        rB_off[g] = r * 128;
        xmB[g] = (r & 7) << 4;
    }
    const int cb0B = ((lane >> 3) & 1) << 4;

    float acc[4][4][4] = {};

    for (int s = 0; s < 4; s++) {
        if (s < 3) CP_WAIT(1); else CP_WAIT(0);
        __syncthreads();

        const uint32_t Abuf = base + (s & 1) * 32768;
        const uint32_t Bbuf = Abuf + 16384;
#pragma unroll
        for (int ks = 0; ks < 4; ks++) {
            uint32_t a[4][4], bf[4][2];
#pragma unroll
            for (int mt = 0; mt < 4; mt++)
                LDSM4(a[mt][0], a[mt][1], a[mt][2], a[mt][3],
                      Abuf + rA_off[mt] + ((ks * 32 + cb0A) ^ xmA[mt]));
#pragma unroll
            for (int g = 0; g < 2; g++) {
                uint32_t r0, r1, r2, r3;
                LDSM4(r0, r1, r2, r3, Bbuf + rB_off[g] + ((ks * 32 + cb0B) ^ xmB[g]));
                bf[2 * g][0] = r0; bf[2 * g][1] = r1;
                bf[2 * g + 1][0] = r2; bf[2 * g + 1][1] = r3;
            }
#pragma unroll
            for (int mt = 0; mt < 4; mt++)
#pragma unroll
                for (int nt = 0; nt < 4; nt++)
                    MMA16816(acc[mt][nt], a[mt][0], a[mt][1], a[mt][2], a[mt][3],
                             bf[nt][0], bf[nt][1]);
        }
        __syncthreads();
        if (s < 2) issue(s + 2);
    }

    // epilogue: transpose (p,c)->E[c][p] (pad 132) then coalesced out stores
    float* E = (float*)smem;
#pragma unroll
    for (int mt = 0; mt < 4; mt++) {
        int pr = wm * 64 + mt * 16 + (lane >> 2);
#pragma unroll
        for (int nt = 0; nt < 4; nt++) {
            int cc = wn * 32 + nt * 8 + (lane & 3) * 2;
            E[cc * 132 + pr]           = acc[mt][nt][0];
            E[(cc + 1) * 132 + pr]     = acc[mt][nt][1];
            E[cc * 132 + pr + 8]       = acc[mt][nt][2];
            E[(cc + 1) * 132 + pr + 8] = acc[mt][nt][3];
        }
    }
    __syncthreads();

    float* ob = out + ((size_t)b * CD + cy * 128) * HW + p0;
#pragma unroll
    for (int i = 0; i < 16; i++) {
        int idx = tid + i * 256;           // 0..4095: 128 c-rows x 32 float4
        int c = idx >> 5, q = idx & 31;
        float4 v = *(float4*)&E[c * 132 + q * 4];
        *(float4*)(ob + (size_t)c * HW + q * 4) = v;
    }
}

// ---------------------------------------------------------------------------
extern "C" void kernel_launch(void* const* d_in, const int* in_sizes, int n_in,
                              void* d_out, int out_size) {
    (void)in_sizes; (void)n_in; (void)out_size;
    const float* feat = (const float*)d_in[0];
    const float* cb   = (const float*)d_in[1];
    const float* pub  = (const float*)d_in[2];
    const float* aff  = (const float*)d_in[3];
    float* out = (float*)d_out;

    cudaFuncSetAttribute(gemm1_mma, cudaFuncAttributeMaxDynamicSharedMemorySize, 98432);
    cudaFuncSetAttribute(gemm2_mma, cudaFuncAttributeMaxDynamicSharedMemorySize, 67712);

    setup_kernel<<<NC, 256>>>(cb, pub, aff);
    prep_kernel<<<NC, 256>>>(cb);

    gemm1_mma<<<dim3(NTILE, 2, NB), 256, 98432>>>(feat);
    warp_softmax_kernel<<<NB * HW / 8, 256>>>();
    gemm2_mma<<<dim3(NTILE, 2, NB), 256, 67712>>>(out);
}

// round 8
// speedup vs baseline: 2.9491x; 1.0061x over previous
#include <cuda_runtime.h>
#include <cuda_fp16.h>
#include <math.h>
#include <stdint.h>

#define B_   4
#define NB   8          // flattened images
#define NC   256        // codes
#define CD   256        // channels
#define H_   96
#define W_   192
#define HW   (H_*W_)    // 18432
#define NTILE 144       // HW/128

// ---------------- global scratch (.bss) ----------------
__device__ __align__(256) __half g_Wt[(size_t)NB * HW * NC];    // sigmoid weights [b][p][n] fp16
__device__ __align__(256) __half g_WsTh[(size_t)NB * HW * NC];  // softmax weights, tile-swizzled fp16
__device__ __align__(256) __half g_B1h[NC * CD];                // cb[n][c]/norm2[n], tiled
__device__ __align__(256) __half g_B2h[NC * CD];                // cb as rows c, k=n, tiled
__device__ float g_norm[NC];
__device__ int   g_masked[NC];
__device__ float g_theta[NB][6];

// ---------------- helpers ----------------
__device__ __forceinline__ uint32_t smem_u32(const void* p) {
    uint32_t a;
    asm("{ .reg .u64 t; cvta.to.shared.u64 t, %1; cvt.u32.u64 %0, t; }" : "=r"(a) : "l"(p));
    return a;
}

// SW128 swizzle: byte offset within a 128-row x 128-byte tile
__device__ __forceinline__ int swz(int row, int bytecol) {
    return row * 128 + (bytecol ^ ((row & 7) << 4));
}

#define LDSM4(d0, d1, d2, d3, a) \
    asm volatile("ldmatrix.sync.aligned.m8n8.x4.shared.b16 {%0,%1,%2,%3}, [%4];" \
                 : "=r"(d0), "=r"(d1), "=r"(d2), "=r"(d3) : "r"(a))

#define MMA16816(d, a0, a1, a2, a3, b0, b1) \
    asm volatile("mma.sync.aligned.m16n8k16.row.col.f32.f16.f16.f32 " \
                 "{%0,%1,%2,%3}, {%4,%5,%6,%7}, {%8,%9}, {%0,%1,%2,%3};" \
                 : "+f"((d)[0]), "+f"((d)[1]), "+f"((d)[2]), "+f"((d)[3]) \
                 : "r"(a0), "r"(a1), "r"(a2), "r"(a3), "r"(b0), "r"(b1))

#define CP16(dst, src) \
    asm volatile("cp.async.cg.shared.global [%0], [%1], 16;" :: "r"(dst), "l"(src))
#define CP_COMMIT() asm volatile("cp.async.commit_group;" ::: "memory")
#define CP_WAIT(n)  asm volatile("cp.async.wait_group %0;" :: "n"(n) : "memory")

// ---------------------------------------------------------------------------
// Setup: per-code norm^2, cosine mask, theta copy.
// ---------------------------------------------------------------------------
__global__ __launch_bounds__(256) void setup_kernel(const float* __restrict__ cb,
                                                    const float* __restrict__ pub,
                                                    const float* __restrict__ aff) {
    __shared__ float red[256];
    const int n = blockIdx.x, t = threadIdx.x;

    float v = cb[n * CD + t];
    red[t] = v * v;
    __syncthreads();
    for (int s = 128; s > 0; s >>= 1) { if (t < s) red[t] += red[t + s]; __syncthreads(); }
    const float cbn2 = red[0];
    __syncthreads();

    const float* cr = cb + n * CD;
    const float* pr = pub + t * CD;
    float dot = 0.f, pn2 = 0.f;
#pragma unroll 8
    for (int c = 0; c < CD; c++) {
        float pv = pr[c];
        dot = fmaf(cr[c], pv, dot);
        pn2 = fmaf(pv, pv, pn2);
    }
    red[t] = dot * rsqrtf(cbn2 * pn2);
    __syncthreads();
    for (int s = 128; s > 0; s >>= 1) { if (t < s) red[t] = fmaxf(red[t], red[t + s]); __syncthreads(); }

    if (t == 0) {
        g_masked[n] = (red[0] <= 0.5f) ? 1 : 0;
        g_norm[n]   = cbn2;
    }
    if (n == 0 && t < NB * 6) g_theta[t / 6][t % 6] = aff[(t / 6) * 12 + (t % 6)];
}

// ---------------------------------------------------------------------------
// Prep: fp16 pre-swizzled operands.
// ---------------------------------------------------------------------------
__global__ __launch_bounds__(256) void prep_kernel(const float* __restrict__ cb) {
    const int r = blockIdx.x, t = threadIdx.x;
    const float inv = 1.f / g_norm[r];

    {   // B1: row n=r, k=c=t
        float x = cb[r * CD + t] * inv;
        int e = (r >> 7) * 32768 + (t >> 6) * 8192 + (swz(r & 127, 2 * (t & 63)) >> 1);
        g_B1h[e] = __float2half(x);
    }
    {   // B2: row c=r, k=n=t
        float x = cb[t * CD + r];
        int e = (r >> 7) * 32768 + (t >> 6) * 8192 + (swz(r & 127, 2 * (t & 63)) >> 1);
        g_B2h[e] = __float2half(x);
    }
}

// ---------------------------------------------------------------------------
// GEMM1: Wt[p][n] = sigmoid( sum_c feat[c][p] * cb[n][c] / norm2[n] )
// CTA: 128p x 128n; grid (2, 144, 8)  (ny fastest -> feat L2 reuse).
// ---------------------------------------------------------------------------
__global__ __launch_bounds__(256) void gemm1_mma(const float* __restrict__ feat) {
    extern __shared__ char smem_raw[];
    uint32_t sb0 = smem_u32(smem_raw);
    uint32_t base = (sb0 + 127u) & ~127u;
    char* smem = smem_raw + (base - sb0);

    const int tid = threadIdx.x;
    const int lane = tid & 31, warp = tid >> 5;
    const int wm = warp >> 2;        // 0..1 -> m offset wm*64
    const int wn = warp & 3;         // 0..3 -> n offset wn*32
    const int b  = blockIdx.z;
    const int ny = blockIdx.x;       // n block 0/1 (fastest: L2 pairing)
    const int p0 = blockIdx.y * 128;

    // issue all B stage copies (4 groups)
    {
        const char* src = (const char*)(g_B1h + ny * 32768);
#pragma unroll
        for (int s = 0; s < 4; s++) {
#pragma unroll
            for (int k = 0; k < 4; k++) {
                int idx = tid + k * 256;
                CP16(base + s * 16384 + idx * 16, src + s * 16384 + idx * 16);
            }
            CP_COMMIT();
        }
    }

    // ldmatrix per-lane address precompute
    int rA_off[4], xmA[4];
#pragma unroll
    for (int mt = 0; mt < 4; mt++) {
        int r = wm * 64 + mt * 16 + (lane & 15);
        rA_off[mt] = r * 128;
        xmA[mt] = (r & 7) << 4;
    }
    const int cb0A = (lane >> 4) << 4;
    int rB_off[2], xmB[2];
#pragma unroll
    for (int g = 0; g < 2; g++) {
        int r = wn * 32 + g * 16 + ((lane >> 4) << 3) + (lane & 7);
        rB_off[g] = r * 128;
        xmB[g] = (r & 7) << 4;
    }
    const int cb0B = ((lane >> 3) & 1) << 4;

    float acc[4][4][4] = {};

    const float* fbase = feat + (size_t)b * CD * HW + p0;
    float ar[32];

    // prologue: load + store stage 0 A
#pragma unroll
    for (int i = 0; i < 16; i++) {
        int idx = tid + i * 256;
        int cp = idx >> 7, p = idx & 127;
        ar[2 * i]     = fbase[(size_t)(2 * cp) * HW + p];
        ar[2 * i + 1] = fbase[(size_t)(2 * cp + 1) * HW + p];
    }
    {
        char* A0 = smem + 65536;
#pragma unroll
        for (int i = 0; i < 16; i++) {
            int idx = tid + i * 256;
            int cp = idx >> 7, p = idx & 127;
            *(__half2*)(A0 + swz(p, 4 * cp)) =
                __floats2half2_rn(ar[2 * i], ar[2 * i + 1]);
        }
    }

    for (int s = 0; s < 4; s++) {
        // prefetch next A stage into regs
        if (s < 3) {
            const float* fs = fbase + (size_t)(s + 1) * 64 * HW;
#pragma unroll
            for (int i = 0; i < 16; i++) {
                int idx = tid + i * 256;
                int cp = idx >> 7, p = idx & 127;
                ar[2 * i]     = fs[(size_t)(2 * cp) * HW + p];
                ar[2 * i + 1] = fs[(size_t)(2 * cp + 1) * HW + p];
            }
        }
        if (s == 0) CP_WAIT(3);
        else if (s == 1) CP_WAIT(2);
        else if (s == 2) CP_WAIT(1);
        else CP_WAIT(0);
        __syncthreads();

        const uint32_t Abuf = base + 65536 + (s & 1) * 16384;
        const uint32_t Bst  = base + s * 16384;
#pragma unroll
        for (int ks = 0; ks < 4; ks++) {
            uint32_t a[4][4], bf[4][2];
#pragma unroll
            for (int mt = 0; mt < 4; mt++)
                LDSM4(a[mt][0], a[mt][1], a[mt][2], a[mt][3],
                      Abuf + rA_off[mt] + ((ks * 32 + cb0A) ^ xmA[mt]));
#pragma unroll
            for (int g = 0; g < 2; g++) {
                uint32_t r0, r1, r2, r3;
                LDSM4(r0, r1, r2, r3, Bst + rB_off[g] + ((ks * 32 + cb0B) ^ xmB[g]));
                bf[2 * g][0] = r0; bf[2 * g][1] = r1;
                bf[2 * g + 1][0] = r2; bf[2 * g + 1][1] = r3;
            }
#pragma unroll
            for (int mt = 0; mt < 4; mt++)
#pragma unroll
                for (int nt = 0; nt < 4; nt++)
                    MMA16816(acc[mt][nt], a[mt][0], a[mt][1], a[mt][2], a[mt][3],
                             bf[nt][0], bf[nt][1]);
        }

        if (s < 3) {
            char* An = smem + 65536 + ((s + 1) & 1) * 16384;
#pragma unroll
            for (int i = 0; i < 16; i++) {
                int idx = tid + i * 256;
                int cp = idx >> 7, p = idx & 127;
                *(__half2*)(An + swz(p, 4 * cp)) =
                    __floats2half2_rn(ar[2 * i], ar[2 * i + 1]);
            }
        }
        __syncthreads();
    }

    // epilogue: sigmoid + fp16 STG (rows p, contiguous n)
    __half* outb = g_Wt + ((size_t)b * HW + p0) * NC + ny * 128;
#pragma unroll
    for (int mt = 0; mt < 4; mt++) {
        int pr = wm * 64 + mt * 16 + (lane >> 2);
#pragma unroll
        for (int nt = 0; nt < 4; nt++) {
            int nc = wn * 32 + nt * 8 + (lane & 3) * 2;
            *(__half2*)(outb + (size_t)pr * NC + nc) =
                __floats2half2_rn(1.f / (1.f + __expf(-acc[mt][nt][0])),
                                  1.f / (1.f + __expf(-acc[mt][nt][1])));
            *(__half2*)(outb + (size_t)(pr + 8) * NC + nc) =
                __floats2half2_rn(1.f / (1.f + __expf(-acc[mt][nt][2])),
                                  1.f / (1.f + __expf(-acc[mt][nt][3])));
        }
    }
}

// ---------------------------------------------------------------------------
// K2: selective warp-affine fill + softmax. 1 warp/pixel. fp16 in/out.
// ---------------------------------------------------------------------------
__global__ __launch_bounds__(256) void warp_softmax_kernel() {
    const int warp = threadIdx.x >> 5, lane = threadIdx.x & 31;
    const int g = blockIdx.x * 8 + warp;
    const int b = g / HW;
    const int p = g - b * HW;

    const __half* own = g_Wt + (size_t)g * NC;
    float v[8];
    {
        uint2 u0 = *(const uint2*)(own + lane * 4);
        uint2 u1 = *(const uint2*)(own + 128 + lane * 4);
        float2 f0 = __half22float2(*(__half2*)&u0.x), f1 = __half22float2(*(__half2*)&u0.y);
        float2 f2 = __half22float2(*(__half2*)&u1.x), f3 = __half22float2(*(__half2*)&u1.y);
        v[0] = f0.x; v[1] = f0.y; v[2] = f1.x; v[3] = f1.y;
        v[4] = f2.x; v[5] = f2.y; v[6] = f3.x; v[7] = f3.y;
    }

    if (b & 1) {   // agent > 0
        const int h = p / W_;
        const int w = p - h * W_;
        const float* th = g_theta[b];
        float gx = 2.f * (float)w / (float)(W_ - 1) - 1.f;
        float gy = 2.f * (float)h / (float)(H_ - 1) - 1.f;
        float cx2 = th[0] * gx + th[1] * gy + th[2];
        float cy2 = th[3] * gx + th[4] * gy + th[5];
        float x = (cx2 + 1.f) * (float)(W_ - 1) * 0.5f;
        float y = (cy2 + 1.f) * (float)(H_ - 1) * 0.5f;
        float x0f = floorf(x), y0f = floorf(y);
        int x0 = (int)x0f, y0 = (int)y0f;
        int x1 = x0 + 1,   y1 = y0 + 1;
        float fx = x - x0f, fy = y - y0f;
        bool vx0 = (x0 >= 0) && (x0 < W_), vx1 = (x1 >= 0) && (x1 < W_);
        bool vy0 = (y0 >= 0) && (y0 < H_), vy1 = (y1 >= 0) && (y1 < H_);
        float wa = (vx0 && vy0) ? (1.f - fx) * (1.f - fy) : 0.f;
        float wb = (vx1 && vy0) ? fx * (1.f - fy)         : 0.f;
        float wc = (vx0 && vy1) ? (1.f - fx) * fy         : 0.f;
        float wd = (vx1 && vy1) ? fx * fy                 : 0.f;
        int cx0 = min(max(x0, 0), W_ - 1), cx1 = min(max(x1, 0), W_ - 1);
        int cy0 = min(max(y0, 0), H_ - 1), cy1 = min(max(y1, 0), H_ - 1);

        const __half* ego = g_Wt + (size_t)(b - 1) * HW * NC;
        const __half* r00 = ego + (size_t)(cy0 * W_ + cx0) * NC;
        const __half* r10 = ego + (size_t)(cy0 * W_ + cx1) * NC;
        const __half* r01 = ego + (size_t)(cy1 * W_ + cx0) * NC;
        const __half* r11 = ego + (size_t)(cy1 * W_ + cx1) * NC;

        int4 m0 = *(const int4*)&g_masked[lane * 4];
        int4 m1 = *(const int4*)&g_masked[128 + lane * 4];
        int mk[8] = {m0.x, m0.y, m0.z, m0.w, m1.x, m1.y, m1.z, m1.w};

#pragma unroll
        for (int half = 0; half < 2; half++) {
            int off = half * 128 + lane * 4;
            uint2 ua = *(const uint2*)(r00 + off);
            uint2 uq = *(const uint2*)(r10 + off);
            uint2 uc = *(const uint2*)(r01 + off);
            uint2 ud = *(const uint2*)(r11 + off);
            float2 a0 = __half22float2(*(__half2*)&ua.x), a1 = __half22float2(*(__half2*)&ua.y);
            float2 q0 = __half22float2(*(__half2*)&uq.x), q1 = __half22float2(*(__half2*)&uq.y);
            float2 c0 = __half22float2(*(__half2*)&uc.x), c1 = __half22float2(*(__half2*)&uc.y);
            float2 d0 = __half22float2(*(__half2*)&ud.x), d1 = __half22float2(*(__half2*)&ud.y);
            float wv[4] = {
                wa * a0.x + wb * q0.x + wc * c0.x + wd * d0.x,
                wa * a0.y + wb * q0.y + wc * c0.y + wd * d0.y,
                wa * a1.x + wb * q1.x + wc * c1.x + wd * d1.x,
                wa * a1.y + wb * q1.y + wc * c1.y + wd * d1.y};
#pragma unroll
            for (int j = 0; j < 4; j++)
                if (mk[half * 4 + j]) v[half * 4 + j] = wv[j];
        }
    }

    float m = v[0];
#pragma unroll
    for (int j = 1; j < 8; j++) m = fmaxf(m, v[j]);
#pragma unroll
    for (int o = 16; o > 0; o >>= 1) m = fmaxf(m, __shfl_xor_sync(0xffffffffu, m, o));
    float e[8]; float s = 0.f;
#pragma unroll
    for (int j = 0; j < 8; j++) { e[j] = expf(v[j] - m); s += e[j]; }
#pragma unroll
    for (int o = 16; o > 0; o >>= 1) s += __shfl_xor_sync(0xffffffffu, s, o);
    float inv = 1.f / s;

    // write tile-swizzled fp16 (GEMM2 A layout)
    const int pl = p & 127;
    const size_t tb = (size_t)(b * NTILE + (p >> 7)) * 32768;
#pragma unroll
    for (int grp = 0; grp < 2; grp++) {
        int n0 = grp * 128 + lane * 4;
        int st = n0 >> 6, nl = n0 & 63;
        size_t eidx = tb + (size_t)st * 8192 + (size_t)(swz(pl, 2 * nl) >> 1);
        *(__half2*)(g_WsTh + eidx)     = __floats2half2_rn(e[grp * 4 + 0] * inv, e[grp * 4 + 1] * inv);
        *(__half2*)(g_WsTh + eidx + 2) = __floats2half2_rn(e[grp * 4 + 2] * inv, e[grp * 4 + 3] * inv);
    }
}

// ---------------------------------------------------------------------------
// GEMM2: out[c][p] = sum_n Ws[p][n] * cb[n][c]
// CTA: 128p x 128c; grid (2, 144, 8) (cy fastest -> WsTh L2 reuse). 2 CTAs/SM.
// ---------------------------------------------------------------------------
__global__ __launch_bounds__(256, 2) void gemm2_mma(float* __restrict__ out) {
    extern __shared__ char smem_raw[];
    uint32_t sb0 = smem_u32(smem_raw);
    uint32_t base = (sb0 + 127u) & ~127u;
    char* smem = smem_raw + (base - sb0);

    const int tid = threadIdx.x;
    const int lane = tid & 31, warp = tid >> 5;
    const int wm = warp >> 2;
    const int wn = warp & 3;
    const int b  = blockIdx.z;
    const int cy = blockIdx.x;       // c block (fastest: L2 pairing)
    const int p0 = blockIdx.y * 128;

    const char* srcA = (const char*)(g_WsTh + (size_t)(b * NTILE + blockIdx.y) * 32768);
    const char* srcB = (const char*)(g_B2h + cy * 32768);

    auto issue = [&](int s) {
        uint32_t dA = base + (s & 1) * 32768;
        uint32_t dB = dA + 16384;
#pragma unroll
        for (int k = 0; k < 4; k++) {
            int idx = tid + k * 256;
            CP16(dA + idx * 16, srcA + (size_t)s * 16384 + idx * 16);
        }
#pragma unroll
        for (int k = 0; k < 4; k++) {
            int idx = tid + k * 256;
            CP16(dB + idx * 16, srcB + (size_t)s * 16384 + idx * 16);
        }
        CP_COMMIT();
    };

    issue(0);
    issue(1);

    int rA_off[4], xmA[4];
#pragma unroll
    for (int mt = 0; mt < 4; mt++) {
        int r = wm * 64 + mt * 16 + (lane & 15);
        rA_off[mt] = r * 128;
        xmA[mt] = (r & 7) << 4;
    }
    const int cb0A = (lane >> 4) << 4;
    int rB_off[2], xmB[2];
#pragma unroll
    for (int g = 0; g < 2; g++) {
        int r = wn * 32 + g * 16 + ((lane >> 4) << 3) + (lane & 7);
        rB_off[g] = r * 128;
        xmB[g] = (r & 7) << 4;
    }
    const int cb0B = ((lane >> 3) & 1) << 4;

    float acc[4][4][4] = {};

    for (int s = 0; s < 4; s++) {
        if (s < 3) CP_WAIT(1); else CP_WAIT(0);
        __syncthreads();

        const uint32_t Abuf = base + (s & 1) * 32768;
        const uint32_t Bbuf = Abuf + 16384;
#pragma unroll
        for (int ks = 0; ks < 4; ks++) {
            uint32_t a[4][4], bf[4][2];
#pragma unroll
            for (int mt = 0; mt < 4; mt++)
                LDSM4(a[mt][0], a[mt][1], a[mt][2], a[mt][3],
                      Abuf + rA_off[mt] + ((ks * 32 + cb0A) ^ xmA[mt]));
#pragma unroll
            for (int g = 0; g < 2; g++) {
                uint32_t r0, r1, r2, r3;
                LDSM4(r0, r1, r2, r3, Bbuf + rB_off[g] + ((ks * 32 + cb0B) ^ xmB[g]));
                bf[2 * g][0] = r0; bf[2 * g][1] = r1;
                bf[2 * g + 1][0] = r2; bf[2 * g + 1][1] = r3;
            }
#pragma unroll
            for (int mt = 0; mt < 4; mt++)
#pragma unroll
                for (int nt = 0; nt < 4; nt++)
                    MMA16816(acc[mt][nt], a[mt][0], a[mt][1], a[mt][2], a[mt][3],
                             bf[nt][0], bf[nt][1]);
        }
        __syncthreads();
        if (s < 2) issue(s + 2);
    }

    // epilogue: transpose (p,c)->E[c][p] (pad 132) then coalesced out stores
    float* E = (float*)smem;
#pragma unroll
    for (int mt = 0; mt < 4; mt++) {
        int pr = wm * 64 + mt * 16 + (lane >> 2);
#pragma unroll
        for (int nt = 0; nt < 4; nt++) {
            int cc = wn * 32 + nt * 8 + (lane & 3) * 2;
            E[cc * 132 + pr]           = acc[mt][nt][0];
            E[(cc + 1) * 132 + pr]     = acc[mt][nt][1];
            E[cc * 132 + pr + 8]       = acc[mt][nt][2];
            E[(cc + 1) * 132 + pr + 8] = acc[mt][nt][3];
        }
    }
    __syncthreads();

    float* ob = out + ((size_t)b * CD + cy * 128) * HW + p0;
#pragma unroll
    for (int i = 0; i < 16; i++) {
        int idx = tid + i * 256;           // 128 c-rows x 32 float4
        int c = idx >> 5, q = idx & 31;
        float4 v = *(float4*)&E[c * 132 + q * 4];
        *(float4*)(ob + (size_t)c * HW + q * 4) = v;
    }
}

// ---------------------------------------------------------------------------
extern "C" void kernel_launch(void* const* d_in, const int* in_sizes, int n_in,
                              void* d_out, int out_size) {
    (void)in_sizes; (void)n_in; (void)out_size;
    const float* feat = (const float*)d_in[0];
    const float* cb   = (const float*)d_in[1];
    const float* pub  = (const float*)d_in[2];
    const float* aff  = (const float*)d_in[3];
    float* out = (float*)d_out;

    cudaFuncSetAttribute(gemm1_mma, cudaFuncAttributeMaxDynamicSharedMemorySize, 98432);
    cudaFuncSetAttribute(gemm2_mma, cudaFuncAttributeMaxDynamicSharedMemorySize, 67712);

    setup_kernel<<<NC, 256>>>(cb, pub, aff);
    prep_kernel<<<NC, 256>>>(cb);

    gemm1_mma<<<dim3(2, NTILE, NB), 256, 98432>>>(feat);
    warp_softmax_kernel<<<NB * HW / 8, 256>>>();
    gemm2_mma<<<dim3(2, NTILE, NB), 256, 67712>>>(out);
}

// round 10
// speedup vs baseline: 4.5096x; 1.5292x over previous
#include <cuda_runtime.h>
#include <cuda_fp16.h>
#include <math.h>
#include <stdint.h>

#define B_   4
#define NB   8          // flattened images
#define NC   256        // codes
#define CD   256        // channels
#define H_   96
#define W_   192
#define HW   (H_*W_)    // 18432
#define NTILE 144       // HW/128

// ---------------- global scratch (.bss) ----------------
__device__ __align__(256) __half g_Wt[(size_t)NB * HW * NC];    // sigmoid weights [b][p][n] fp16
__device__ __align__(256) __half g_WsTh[(size_t)NB * HW * NC];  // softmax weights, tile-swizzled fp16
__device__ __align__(256) __half g_B1h[NC * CD];                // cb[n][c]/norm2[n], tiled
__device__ __align__(256) __half g_B2h[NC * CD];                // cb as rows c, k=n, tiled
__device__ float g_norm[NC];
__device__ int   g_masked[NC];
__device__ float g_theta[NB][6];

// ---------------- helpers ----------------
__device__ __forceinline__ uint32_t smem_u32(const void* p) {
    uint32_t a;
    asm("{ .reg .u64 t; cvta.to.shared.u64 t, %1; cvt.u32.u64 %0, t; }" : "=r"(a) : "l"(p));
    return a;
}

// SW128 swizzle: byte offset within a 128-row x 128-byte tile
__device__ __forceinline__ int swz(int row, int bytecol) {
    return row * 128 + (bytecol ^ ((row & 7) << 4));
}

#define LDSM4(d0, d1, d2, d3, a) \
    asm volatile("ldmatrix.sync.aligned.m8n8.x4.shared.b16 {%0,%1,%2,%3}, [%4];" \
                 : "=r"(d0), "=r"(d1), "=r"(d2), "=r"(d3) : "r"(a))

// fp32-accumulate (GEMM2)
#define MMA16816(d, a0, a1, a2, a3, b0, b1) \
    asm volatile("mma.sync.aligned.m16n8k16.row.col.f32.f16.f16.f32 " \
                 "{%0,%1,%2,%3}, {%4,%5,%6,%7}, {%8,%9}, {%0,%1,%2,%3};" \
                 : "+f"((d)[0]), "+f"((d)[1]), "+f"((d)[2]), "+f"((d)[3]) \
                 : "r"(a0), "r"(a1), "r"(a2), "r"(a3), "r"(b0), "r"(b1))

// fp16-accumulate (GEMM1)
#define MMA16816H(d, a0, a1, a2, a3, b0, b1) \
    asm volatile("mma.sync.aligned.m16n8k16.row.col.f16.f16.f16.f16 " \
                 "{%0,%1}, {%2,%3,%4,%5}, {%6,%7}, {%0,%1};" \
                 : "+r"((d)[0]), "+r"((d)[1]) \
                 : "r"(a0), "r"(a1), "r"(a2), "r"(a3), "r"(b0), "r"(b1))

#define CP16(dst, src) \
    asm volatile("cp.async.cg.shared.global [%0], [%1], 16;" :: "r"(dst), "l"(src))
#define CP_COMMIT() asm volatile("cp.async.commit_group;" ::: "memory")
#define CP_WAIT(n)  asm volatile("cp.async.wait_group %0;" :: "n"(n) : "memory")

// ---------------------------------------------------------------------------
// Setup: per-code norm^2, cosine mask, theta copy. Warp-coalesced pub scan.
// ---------------------------------------------------------------------------
__global__ __launch_bounds__(256) void setup_kernel(const float* __restrict__ cb,
                                                    const float* __restrict__ pub,
                                                    const float* __restrict__ aff) {
    __shared__ float cbrow[256];
    __shared__ float sqs[8];
    __shared__ float wmaxs[8];
    const int n = blockIdx.x, t = threadIdx.x;
    const int w = t >> 5, l = t & 31;

    float v = cb[n * CD + t];
    cbrow[t] = v;
    float sq = v * v;
#pragma unroll
    for (int o = 16; o > 0; o >>= 1) sq += __shfl_xor_sync(0xffffffffu, sq, o);
    if (l == 0) sqs[w] = sq;
    __syncthreads();
    float cbn2 = 0.f;
#pragma unroll
    for (int i = 0; i < 8; i++) cbn2 += sqs[i];

    // warp w handles pub rows w*32 .. w*32+31; lane-parallel dot
    float wmax = -1e30f;
    for (int i = 0; i < 32; i++) {
        const int r = w * 32 + i;
        const float* pr = pub + r * CD + l * 8;
        const float* cr = cbrow + l * 8;
        float dot = 0.f, pn2 = 0.f;
#pragma unroll
        for (int j = 0; j < 2; j++) {
            float4 p4 = *(const float4*)(pr + j * 4);
            float4 c4 = *(const float4*)(cr + j * 4);
            dot += p4.x * c4.x + p4.y * c4.y + p4.z * c4.z + p4.w * c4.w;
            pn2 += p4.x * p4.x + p4.y * p4.y + p4.z * p4.z + p4.w * p4.w;
        }
#pragma unroll
        for (int o = 16; o > 0; o >>= 1) {
            dot += __shfl_xor_sync(0xffffffffu, dot, o);
            pn2 += __shfl_xor_sync(0xffffffffu, pn2, o);
        }
        wmax = fmaxf(wmax, dot * rsqrtf(cbn2 * pn2));
    }
    if (l == 0) wmaxs[w] = wmax;
    __syncthreads();
    if (t == 0) {
        float m = wmaxs[0];
#pragma unroll
        for (int i = 1; i < 8; i++) m = fmaxf(m, wmaxs[i]);
        g_masked[n] = (m <= 0.5f) ? 1 : 0;
        g_norm[n]   = cbn2;
    }
    if (n == 0 && t < NB * 6) g_theta[t / 6][t % 6] = aff[(t / 6) * 12 + (t % 6)];
}

// ---------------------------------------------------------------------------
// Prep: fp16 pre-swizzled operands.
// ---------------------------------------------------------------------------
__global__ __launch_bounds__(256) void prep_kernel(const float* __restrict__ cb) {
    const int r = blockIdx.x, t = threadIdx.x;
    const float inv = 1.f / g_norm[r];

    {   // B1: row n=r, k=c=t
        float x = cb[r * CD + t] * inv;
        int e = (r >> 7) * 32768 + (t >> 6) * 8192 + (swz(r & 127, 2 * (t & 63)) >> 1);
        g_B1h[e] = __float2half(x);
    }
    {   // B2: row c=r, k=n=t
        float x = cb[t * CD + r];
        int e = (r >> 7) * 32768 + (t >> 6) * 8192 + (swz(r & 127, 2 * (t & 63)) >> 1);
        g_B2h[e] = __float2half(x);
    }
}

// ---------------------------------------------------------------------------
// GEMM1: Wt[p][n] = sigmoid( sum_c feat[c][p] * cb[n][c] / norm2[n] )
// fp16 accumulators. CTA: 128p x 128n; grid (2, 144, 8); 2 CTAs/SM.
// ---------------------------------------------------------------------------
__global__ __launch_bounds__(256, 2) void gemm1_mma(const float* __restrict__ feat) {
    extern __shared__ char smem_raw[];
    uint32_t sb0 = smem_u32(smem_raw);
    uint32_t base = (sb0 + 127u) & ~127u;
    char* smem = smem_raw + (base - sb0);

    const int tid = threadIdx.x;
    const int lane = tid & 31, warp = tid >> 5;
    const int wm = warp >> 2;        // 0..1 -> m offset wm*64
    const int wn = warp & 3;         // 0..3 -> n offset wn*32
    const int b  = blockIdx.z;
    const int ny = blockIdx.x;       // n block 0/1 (fastest: L2 pairing)
    const int p0 = blockIdx.y * 128;

    // issue all B stage copies (4 groups)
    {
        const char* src = (const char*)(g_B1h + ny * 32768);
#pragma unroll
        for (int s = 0; s < 4; s++) {
#pragma unroll
            for (int k = 0; k < 4; k++) {
                int idx = tid + k * 256;
                CP16(base + s * 16384 + idx * 16, src + s * 16384 + idx * 16);
            }
            CP_COMMIT();
        }
    }

    // ldmatrix per-lane address precompute
    int rA_off[4], xmA[4];
#pragma unroll
    for (int mt = 0; mt < 4; mt++) {
        int r = wm * 64 + mt * 16 + (lane & 15);
        rA_off[mt] = r * 128;
        xmA[mt] = (r & 7) << 4;
    }
    const int cb0A = (lane >> 4) << 4;
    int rB_off[2], xmB[2];
#pragma unroll
    for (int g = 0; g < 2; g++) {
        int r = wn * 32 + g * 16 + ((lane >> 4) << 3) + (lane & 7);
        rB_off[g] = r * 128;
        xmB[g] = (r & 7) << 4;
    }
    const int cb0B = ((lane >> 3) & 1) << 4;

    uint32_t acc[4][4][2];
#pragma unroll
    for (int i = 0; i < 4; i++)
#pragma unroll
        for (int j = 0; j < 4; j++) { acc[i][j][0] = 0u; acc[i][j][1] = 0u; }

    const float* fbase = feat + (size_t)b * CD * HW + p0;
    float ar[32];

    // prologue: load + store stage 0 A
#pragma unroll
    for (int i = 0; i < 16; i++) {
        int idx = tid + i * 256;
        int cp = idx >> 7, p = idx & 127;
        ar[2 * i]     = fbase[(size_t)(2 * cp) * HW + p];
        ar[2 * i + 1] = fbase[(size_t)(2 * cp + 1) * HW + p];
    }
    {
        char* A0 = smem + 65536;
#pragma unroll
        for (int i = 0; i < 16; i++) {
            int idx = tid + i * 256;
            int cp = idx >> 7, p = idx & 127;
            *(__half2*)(A0 + swz(p, 4 * cp)) =
                __floats2half2_rn(ar[2 * i], ar[2 * i + 1]);
        }
    }

    for (int s = 0; s < 4; s++) {
        // prefetch next A stage into regs
        if (s < 3) {
            const float* fs = fbase + (size_t)(s + 1) * 64 * HW;
#pragma unroll
            for (int i = 0; i < 16; i++) {
                int idx = tid + i * 256;
                int cp = idx >> 7, p = idx & 127;
                ar[2 * i]     = fs[(size_t)(2 * cp) * HW + p];
                ar[2 * i + 1] = fs[(size_t)(2 * cp + 1) * HW + p];
            }
        }
        if (s == 0) CP_WAIT(3);
        else if (s == 1) CP_WAIT(2);
        else if (s == 2) CP_WAIT(1);
        else CP_WAIT(0);
        __syncthreads();

        const uint32_t Abuf = base + 65536 + (s & 1) * 16384;
        const uint32_t Bst  = base + s * 16384;
#pragma unroll
        for (int ks = 0; ks < 4; ks++) {
            uint32_t a[4][4], bf[4][2];
#pragma unroll
            for (int mt = 0; mt < 4; mt++)
                LDSM4(a[mt][0], a[mt][1], a[mt][2], a[mt][3],
                      Abuf + rA_off[mt] + ((ks * 32 + cb0A) ^ xmA[mt]));
#pragma unroll
            for (int g = 0; g < 2; g++) {
                uint32_t r0, r1, r2, r3;
                LDSM4(r0, r1, r2, r3, Bst + rB_off[g] + ((ks * 32 + cb0B) ^ xmB[g]));
                bf[2 * g][0] = r0; bf[2 * g][1] = r1;
                bf[2 * g + 1][0] = r2; bf[2 * g + 1][1] = r3;
            }
#pragma unroll
            for (int mt = 0; mt < 4; mt++)
#pragma unroll
                for (int nt = 0; nt < 4; nt++)
                    MMA16816H(acc[mt][nt], a[mt][0], a[mt][1], a[mt][2], a[mt][3],
                              bf[nt][0], bf[nt][1]);
        }

        if (s < 3) {
            char* An = smem + 65536 + ((s + 1) & 1) * 16384;
#pragma unroll
            for (int i = 0; i < 16; i++) {
                int idx = tid + i * 256;
                int cp = idx >> 7, p = idx & 127;
                *(__half2*)(An + swz(p, 4 * cp)) =
                    __floats2half2_rn(ar[2 * i], ar[2 * i + 1]);
            }
        }
        __syncthreads();
    }

    // epilogue: sigmoid + fp16 STG (rows p, contiguous n)
    __half* outb = g_Wt + ((size_t)b * HW + p0) * NC + ny * 128;
#pragma unroll
    for (int mt = 0; mt < 4; mt++) {
        int pr = wm * 64 + mt * 16 + (lane >> 2);
#pragma unroll
        for (int nt = 0; nt < 4; nt++) {
            int nc = wn * 32 + nt * 8 + (lane & 3) * 2;
            float2 f0 = __half22float2(*(__half2*)&acc[mt][nt][0]);   // row pr
            float2 f1 = __half22float2(*(__half2*)&acc[mt][nt][1]);   // row pr+8
            *(__half2*)(outb + (size_t)pr * NC + nc) =
                __floats2half2_rn(1.f / (1.f + __expf(-f0.x)),
                                  1.f / (1.f + __expf(-f0.y)));
            *(__half2*)(outb + (size_t)(pr + 8) * NC + nc) =
                __floats2half2_rn(1.f / (1.f + __expf(-f1.x)),
                                  1.f / (1.f + __expf(-f1.y)));
        }
    }
}

// ---------------------------------------------------------------------------
// K2: selective warp-affine fill + softmax. 1 warp/pixel. fp16 in/out.
// ---------------------------------------------------------------------------
__global__ __launch_bounds__(256) void warp_softmax_kernel() {
    const int warp = threadIdx.x >> 5, lane = threadIdx.x & 31;
    const int g = blockIdx.x * 8 + warp;
    const int b = g / HW;
    const int p = g - b * HW;

    const __half* own = g_Wt + (size_t)g * NC;
    float v[8];
    {
        uint2 u0 = *(const uint2*)(own + lane * 4);
        uint2 u1 = *(const uint2*)(own + 128 + lane * 4);
        float2 f0 = __half22float2(*(__half2*)&u0.x), f1 = __half22float2(*(__half2*)&u0.y);
        float2 f2 = __half22float2(*(__half2*)&u1.x), f3 = __half22float2(*(__half2*)&u1.y);
        v[0] = f0.x; v[1] = f0.y; v[2] = f1.x; v[3] = f1.y;
        v[4] = f2.x; v[5] = f2.y; v[6] = f3.x; v[7] = f3.y;
    }

    if (b & 1) {   // agent > 0
        const int h = p / W_;
        const int w = p - h * W_;
        const float* th = g_theta[b];
        float gx = 2.f * (float)w / (float)(W_ - 1) - 1.f;
        float gy = 2.f * (float)h / (float)(H_ - 1) - 1.f;
        float cx2 = th[0] * gx + th[1] * gy + th[2];
        float cy2 = th[3] * gx + th[4] * gy + th[5];
        float x = (cx2 + 1.f) * (float)(W_ - 1) * 0.5f;
        float y = (cy2 + 1.f) * (float)(H_ - 1) * 0.5f;
        float x0f = floorf(x), y0f = floorf(y);
        int x0 = (int)x0f, y0 = (int)y0f;
        int x1 = x0 + 1,   y1 = y0 + 1;
        float fx = x - x0f, fy = y - y0f;
        bool vx0 = (x0 >= 0) && (x0 < W_), vx1 = (x1 >= 0) && (x1 < W_);
        bool vy0 = (y0 >= 0) && (y0 < H_), vy1 = (y1 >= 0) && (y1 < H_);
        float wa = (vx0 && vy0) ? (1.f - fx) * (1.f - fy) : 0.f;
        float wb = (vx1 && vy0) ? fx * (1.f - fy)         : 0.f;
        float wc = (vx0 && vy1) ? (1.f - fx) * fy         : 0.f;
        float wd = (vx1 && vy1) ? fx * fy                 : 0.f;
        int cx0 = min(max(x0, 0), W_ - 1), cx1 = min(max(x1, 0), W_ - 1);
        int cy0 = min(max(y0, 0), H_ - 1), cy1 = min(max(y1, 0), H_ - 1);

        const __half* ego = g_Wt + (size_t)(b - 1) * HW * NC;
        const __half* r00 = ego + (size_t)(cy0 * W_ + cx0) * NC;
        const __half* r10 = ego + (size_t)(cy0 * W_ + cx1) * NC;
        const __half* r01 = ego + (size_t)(cy1 * W_ + cx0) * NC;
        const __half* r11 = ego + (size_t)(cy1 * W_ + cx1) * NC;

        int4 m0 = *(const int4*)&g_masked[lane * 4];
        int4 m1 = *(const int4*)&g_masked[128 + lane * 4];
        int mk[8] = {m0.x, m0.y, m0.z, m0.w, m1.x, m1.y, m1.z, m1.w};

#pragma unroll
        for (int half = 0; half < 2; half++) {
            int off = half * 128 + lane * 4;
            uint2 ua = *(const uint2*)(r00 + off);
            uint2 uq = *(const uint2*)(r10 + off);
            uint2 uc = *(const uint2*)(r01 + off);
            uint2 ud = *(const uint2*)(r11 + off);
            float2 a0 = __half22float2(*(__half2*)&ua.x), a1 = __half22float2(*(__half2*)&ua.y);
            float2 q0 = __half22float2(*(__half2*)&uq.x), q1 = __half22float2(*(__half2*)&uq.y);
            float2 c0 = __half22float2(*(__half2*)&uc.x), c1 = __half22float2(*(__half2*)&uc.y);
            float2 d0 = __half22float2(*(__half2*)&ud.x), d1 = __half22float2(*(__half2*)&ud.y);
            float wv[4] = {
                wa * a0.x + wb * q0.x + wc * c0.x + wd * d0.x,
                wa * a0.y + wb * q0.y + wc * c0.y + wd * d0.y,
                wa * a1.x + wb * q1.x + wc * c1.x + wd * d1.x,
                wa * a1.y + wb * q1.y + wc * c1.y + wd * d1.y};
#pragma unroll
            for (int j = 0; j < 4; j++)
                if (mk[half * 4 + j]) v[half * 4 + j] = wv[j];
        }
    }

    float m = v[0];
#pragma unroll
    for (int j = 1; j < 8; j++) m = fmaxf(m, v[j]);
#pragma unroll
    for (int o = 16; o > 0; o >>= 1) m = fmaxf(m, __shfl_xor_sync(0xffffffffu, m, o));
    float e[8]; float s = 0.f;
#pragma unroll
    for (int j = 0; j < 8; j++) { e[j] = __expf(v[j] - m); s += e[j]; }
#pragma unroll
    for (int o = 16; o > 0; o >>= 1) s += __shfl_xor_sync(0xffffffffu, s, o);
    float inv = 1.f / s;

    // write tile-swizzled fp16 (GEMM2 A layout)
    const int pl = p & 127;
    const size_t tb = (size_t)(b * NTILE + (p >> 7)) * 32768;
#pragma unroll
    for (int grp = 0; grp < 2; grp++) {
        int n0 = grp * 128 + lane * 4;
        int st = n0 >> 6, nl = n0 & 63;
        size_t eidx = tb + (size_t)st * 8192 + (size_t)(swz(pl, 2 * nl) >> 1);
        *(__half2*)(g_WsTh + eidx)     = __floats2half2_rn(e[grp * 4 + 0] * inv, e[grp * 4 + 1] * inv);
        *(__half2*)(g_WsTh + eidx + 2) = __floats2half2_rn(e[grp * 4 + 2] * inv, e[grp * 4 + 3] * inv);
    }
}

// ---------------------------------------------------------------------------
// GEMM2: out[c][p] = sum_n Ws[p][n] * cb[n][c]   (fp32 accumulate)
// CTA: 128p x 128c; grid (2, 144, 8) (cy fastest -> WsTh L2 reuse). 2 CTAs/SM.
// ---------------------------------------------------------------------------
__global__ __launch_bounds__(256, 2) void gemm2_mma(float* __restrict__ out) {
    extern __shared__ char smem_raw[];
    uint32_t sb0 = smem_u32(smem_raw);
    uint32_t base = (sb0 + 127u) & ~127u;
    char* smem = smem_raw + (base - sb0);

    const int tid = threadIdx.x;
    const int lane = tid & 31, warp = tid >> 5;
    const int wm = warp >> 2;
    const int wn = warp & 3;
    const int b  = blockIdx.z;
    const int cy = blockIdx.x;       // c block (fastest: L2 pairing)
    const int p0 = blockIdx.y * 128;

    const char* srcA = (const char*)(g_WsTh + (size_t)(b * NTILE + blockIdx.y) * 32768);
    const char* srcB = (const char*)(g_B2h + cy * 32768);

    auto issue = [&](int s) {
        uint32_t dA = base + (s & 1) * 32768;
        uint32_t dB = dA + 16384;
#pragma unroll
        for (int k = 0; k < 4; k++) {
            int idx = tid + k * 256;
            CP16(dA + idx * 16, srcA + (size_t)s * 16384 + idx * 16);
        }
#pragma unroll
        for (int k = 0; k < 4; k++) {
            int idx = tid + k * 256;
            CP16(dB + idx * 16, srcB + (size_t)s * 16384 + idx * 16);
        }
        CP_COMMIT();
    };

    issue(0);
    issue(1);

    int rA_off[4], xmA[4];
#pragma unroll
    for (int mt = 0; mt < 4; mt++) {
        int r = wm * 64 + mt * 16 + (lane & 15);
        rA_off[mt] = r * 128;
        xmA[mt] = (r & 7) << 4;
    }
    const int cb0A = (lane >> 4) << 4;
    int rB_off[2], xmB[2];
#pragma unroll
    for (int g = 0; g < 2; g++) {
        int r = wn * 32 + g * 16 + ((lane >> 4) << 3) + (lane & 7);
        rB_off[g] = r * 128;
        xmB[g] = (r & 7) << 4;
    }
    const int cb0B = ((lane >> 3) & 1) << 4;

    float acc[4][4][4] = {};

    for (int s = 0; s < 4; s++) {
        if (s < 3) CP_WAIT(1); else CP_WAIT(0);
        __syncthreads();

        const uint32_t Abuf = base + (s & 1) * 32768;
        const uint32_t Bbuf = Abuf + 16384;
#pragma unroll
        for (int ks = 0; ks < 4; ks++) {
            uint32_t a[4][4], bf[4][2];
#pragma unroll
            for (int mt = 0; mt < 4; mt++)
                LDSM4(a[mt][0], a[mt][1], a[mt][2], a[mt][3],
                      Abuf + rA_off[mt] + ((ks * 32 + cb0A) ^ xmA[mt]));
#pragma unroll
            for (int g = 0; g < 2; g++) {
                uint32_t r0, r1, r2, r3;
                LDSM4(r0, r1, r2, r3, Bbuf + rB_off[g] + ((ks * 32 + cb0B) ^ xmB[g]));
                bf[2 * g][0] = r0; bf[2 * g][1] = r1;
                bf[2 * g + 1][0] = r2; bf[2 * g + 1][1] = r3;
            }
#pragma unroll
            for (int mt = 0; mt < 4; mt++)
#pragma unroll
                for (int nt = 0; nt < 4; nt++)
                    MMA16816(acc[mt][nt], a[mt][0], a[mt][1], a[mt][2], a[mt][3],
                             bf[nt][0], bf[nt][1]);
        }
        __syncthreads();
        if (s < 2) issue(s + 2);
    }

    // epilogue: transpose (p,c)->E[c][p] (pad 132) then coalesced out stores
    float* E = (float*)smem;
#pragma unroll
    for (int mt = 0; mt < 4; mt++) {
        int pr = wm * 64 + mt * 16 + (lane >> 2);
#pragma unroll
        for (int nt = 0; nt < 4; nt++) {
            int cc = wn * 32 + nt * 8 + (lane & 3) * 2;
            E[cc * 132 + pr]           = acc[mt][nt][0];
            E[(cc + 1) * 132 + pr]     = acc[mt][nt][1];
            E[cc * 132 + pr + 8]       = acc[mt][nt][2];
            E[(cc + 1) * 132 + pr + 8] = acc[mt][nt][3];
        }
    }
    __syncthreads();

    float* ob = out + ((size_t)b * CD + cy * 128) * HW + p0;
#pragma unroll
    for (int i = 0; i < 16; i++) {
        int idx = tid + i * 256;           // 128 c-rows x 32 float4
        int c = idx >> 5, q = idx & 31;
        float4 v = *(float4*)&E[c * 132 + q * 4];
        *(float4*)(ob + (size_t)c * HW + q * 4) = v;
    }
}

// ---------------------------------------------------------------------------
extern "C" void kernel_launch(void* const* d_in, const int* in_sizes, int n_in,
                              void* d_out, int out_size) {
    (void)in_sizes; (void)n_in; (void)out_size;
    const float* feat = (const float*)d_in[0];
    const float* cb   = (const float*)d_in[1];
    const float* pub  = (const float*)d_in[2];
    const float* aff  = (const float*)d_in[3];
    float* out = (float*)d_out;

    cudaFuncSetAttribute(gemm1_mma, cudaFuncAttributeMaxDynamicSharedMemorySize, 98432);
    cudaFuncSetAttribute(gemm2_mma, cudaFuncAttributeMaxDynamicSharedMemorySize, 67712);

    setup_kernel<<<NC, 256>>>(cb, pub, aff);
    prep_kernel<<<NC, 256>>>(cb);

    gemm1_mma<<<dim3(2, NTILE, NB), 256, 98432>>>(feat);
    warp_softmax_kernel<<<NB * HW / 8, 256>>>();
    gemm2_mma<<<dim3(2, NTILE, NB), 256, 67712>>>(out);
}